// round 15
// baseline (speedup 1.0000x reference)
#include <cuda_runtime.h>
#include <cuda_bf16.h>
#include <cstdint>

#define LNUM 18
#define BB 8
#define CC 50
#define AA 32
#define HH 1024
#define NHH 8
#define HD 256
#define PP 800
#define MLPD 4096
#define MTOT 400
#define TTOT 850
#define TP 896
#define CP 64
#define MPAD 512
#define QKVLD 2560
#define SMEM_GEMM (96*1024)
#define KVSTRIDE (BB*TP*HD)
#define NQ_ITEMS (MTOT*NHH*128)
#define NKNEW_ITEMS (BB*CC*128)
#define NVNEW_ITEMS (BB*CC*HD)

typedef __nv_bfloat16 bf16;

// ---------------- fp32 scratch ----------------
__device__ __align__(256) float g_x[MTOT*HH];
__device__ __align__(256) float g_qkv[2*MTOT*QKVLD];
__device__ __align__(256) float g_s[BB*NHH*CP*TP];
__device__ __align__(256) float g_gate[MTOT*HH];   // prologue t_in scratch only

// ---------------- bf16 activations (hi/lo) ----------------
__device__ __align__(256) bf16 g_hh[MPAD*HH];
__device__ __align__(256) bf16 g_hl[MPAD*HH];
__device__ __align__(256) bf16 g_xth[MPAD*2*HH];
__device__ __align__(256) bf16 g_xtl[MPAD*2*HH];
__device__ __align__(256) bf16 g_midh[MPAD*MLPD];
__device__ __align__(256) bf16 g_midl[MPAD*MLPD];
__device__ __align__(256) bf16 g_aoh[MPAD*NHH*HD];
__device__ __align__(256) bf16 g_aol[MPAD*NHH*HD];
__device__ __align__(256) bf16 g_nh[MPAD*64];
__device__ __align__(256) bf16 g_nl[MPAD*64];

// ---------------- bf16 attention operands (KV double-buffered by layer parity) ----------------
__device__ __align__(256) bf16 g_qh[BB*NHH*CP*HD];
__device__ __align__(256) bf16 g_ql[BB*NHH*CP*HD];
__device__ __align__(256) bf16 g_kh[2*KVSTRIDE];
__device__ __align__(256) bf16 g_kl[2*KVSTRIDE];
__device__ __align__(256) bf16 g_vh[2*KVSTRIDE];
__device__ __align__(256) bf16 g_vl[2*KVSTRIDE];
__device__ __align__(256) bf16 g_sh[BB*NHH*CP*TP];
__device__ __align__(256) bf16 g_sl[BB*NHH*CP*TP];

// ---------------- bf16 weights (hi/lo) ----------------
__device__ bf16 g_qwh[LNUM*2048*1024];
__device__ bf16 g_qwl[LNUM*2048*1024];
__device__ bf16 g_kwh[LNUM*256*1024];
__device__ bf16 g_kwl[LNUM*256*1024];
__device__ bf16 g_vwh[LNUM*256*1024];
__device__ bf16 g_vwl[LNUM*256*1024];
__device__ bf16 g_owh[LNUM*1024*2048];
__device__ bf16 g_owl[LNUM*1024*2048];
__device__ bf16 g_gwh[LNUM*4096*1024];
__device__ bf16 g_gwl[LNUM*4096*1024];
__device__ bf16 g_uwh[LNUM*4096*1024];
__device__ bf16 g_uwl[LNUM*4096*1024];
__device__ bf16 g_dwh[LNUM*1024*4096];
__device__ bf16 g_dwl[LNUM*1024*4096];
__device__ bf16 g_tinh[1024*2048];
__device__ bf16 g_tinl[1024*2048];
__device__ bf16 g_touth[1024*1024];
__device__ bf16 g_toutl[1024*1024];
__device__ bf16 g_outwh[64*1024];
__device__ bf16 g_outwl[64*1024];
__device__ bf16 g_inwh[1024*64];
__device__ bf16 g_inwl[1024*64];

// ---------------- helpers ----------------
__device__ __forceinline__ unsigned su32(const void* p){ return (unsigned)__cvta_generic_to_shared(p); }
__device__ __forceinline__ int swz(int r, int cb){ return r*128 + (cb ^ ((r&7)<<4)); }

__device__ __forceinline__ void ldsm4(unsigned& a,unsigned& b,unsigned& c,unsigned& d, unsigned addr){
  asm volatile("ldmatrix.sync.aligned.m8n8.x4.shared.b16 {%0,%1,%2,%3},[%4];"
    :"=r"(a),"=r"(b),"=r"(c),"=r"(d):"r"(addr));
}
__device__ __forceinline__ void ldsm4t(unsigned& a,unsigned& b,unsigned& c,unsigned& d, unsigned addr){
  asm volatile("ldmatrix.sync.aligned.m8n8.x4.trans.shared.b16 {%0,%1,%2,%3},[%4];"
    :"=r"(a),"=r"(b),"=r"(c),"=r"(d):"r"(addr));
}
__device__ __forceinline__ void mma16816(float* c, const unsigned* a, unsigned b0, unsigned b1){
  asm volatile("mma.sync.aligned.m16n8k16.row.col.f32.bf16.bf16.f32 {%0,%1,%2,%3},{%4,%5,%6,%7},{%8,%9},{%0,%1,%2,%3};"
    :"+f"(c[0]),"+f"(c[1]),"+f"(c[2]),"+f"(c[3])
    :"r"(a[0]),"r"(a[1]),"r"(a[2]),"r"(a[3]),"r"(b0),"r"(b1));
}
__device__ __forceinline__ void split1(float x, unsigned short& h, unsigned short& l){
  __nv_bfloat16 bh = __float2bfloat16_rn(x);
  h = __bfloat16_as_ushort(bh);
  l = __bfloat16_as_ushort(__float2bfloat16_rn(x - __bfloat162float(bh)));
}
__device__ __forceinline__ void cpa16(void* sdst, const void* gsrc){
  unsigned d = su32(sdst);
  asm volatile("cp.async.cg.shared.global [%0],[%1],16;" :: "r"(d),"l"(gsrc));
}

// grid-stride fp32 -> bf16 hi/lo conversion over n4 float4 elements
__device__ __forceinline__ void conv_gs(const float* __restrict__ src,
  bf16* __restrict__ h, bf16* __restrict__ l, int n4, int cb, int nb)
{
  for (int i = cb*256 + (int)threadIdx.x; i < n4; i += nb*256) {
    float4 v = ((const float4*)src)[i];
    unsigned short h0,l0,h1,l1,h2,l2,h3,l3;
    split1(v.x,h0,l0); split1(v.y,h1,l1); split1(v.z,h2,l2); split1(v.w,h3,l3);
    ((uint2*)h)[i] = make_uint2((unsigned)h0|((unsigned)h1<<16), (unsigned)h2|((unsigned)h3<<16));
    ((uint2*)l)[i] = make_uint2((unsigned)l0|((unsigned)l1<<16), (unsigned)l2|((unsigned)l3<<16));
  }
}

// KV prefix conversion for layer nl into parity buffer (nl&1)
__device__ __forceinline__ void conv_kvprefix(const float* __restrict__ pk, const float* __restrict__ pv,
  int nl, bf16* kh, bf16* kl, bf16* vh, bf16* vl, int cb, int nb)
{
  const int n4 = BB*PP*HD/4;
  const float* srcK = pk + (size_t)nl*BB*PP*HD;
  const float* srcV = pv + (size_t)nl*BB*PP*HD;
  size_t bo = (size_t)(nl&1)*KVSTRIDE;
  bf16* dkh = kh + bo; bf16* dkl = kl + bo;
  bf16* dvh = vh + bo; bf16* dvl = vl + bo;
  for (int i = cb*256 + (int)threadIdx.x; i < n4; i += nb*256) {
    int e0 = i*4;
    int d = e0 & 255;
    int bt = e0 >> 8;
    int t = bt % PP, b = bt / PP;
    size_t dst = ((size_t)b*TP + t)*HD + d;
    unsigned short h0,l0,h1,l1,h2,l2,h3,l3;
    float4 v = ((const float4*)srcK)[i];
    split1(v.x,h0,l0); split1(v.y,h1,l1); split1(v.z,h2,l2); split1(v.w,h3,l3);
    *(uint2*)(dkh+dst) = make_uint2((unsigned)h0|((unsigned)h1<<16), (unsigned)h2|((unsigned)h3<<16));
    *(uint2*)(dkl+dst) = make_uint2((unsigned)l0|((unsigned)l1<<16), (unsigned)l2|((unsigned)l3<<16));
    v = ((const float4*)srcV)[i];
    split1(v.x,h0,l0); split1(v.y,h1,l1); split1(v.z,h2,l2); split1(v.w,h3,l3);
    *(uint2*)(dvh+dst) = make_uint2((unsigned)h0|((unsigned)h1<<16), (unsigned)h2|((unsigned)h3<<16));
    *(uint2*)(dvl+dst) = make_uint2((unsigned)l0|((unsigned)l1<<16), (unsigned)l2|((unsigned)l3<<16));
  }
}

__global__ void kvprefix_kernel(const float* __restrict__ pk, const float* __restrict__ pv,
  int nl, bf16* kh, bf16* kl, bf16* vh, bf16* vl)
{
  conv_kvprefix(pk, pv, nl, kh, kl, vh, vl, blockIdx.x, gridDim.x);
}

__device__ __forceinline__ float blk_reduce(float v, bool ismax) {
    __shared__ float sh[8];
    int lane = threadIdx.x & 31, wid = threadIdx.x >> 5;
    #pragma unroll
    for (int o = 16; o > 0; o >>= 1) {
        float w = __shfl_xor_sync(0xffffffffu, v, o);
        v = ismax ? fmaxf(v, w) : (v + w);
    }
    if (lane == 0) sh[wid] = v;
    __syncthreads();
    if (threadIdx.x == 0) {
        float r = sh[0];
        int nw = (blockDim.x + 31) >> 5;
        for (int i = 1; i < nw; i++) r = ismax ? fmaxf(r, sh[i]) : (r + sh[i]);
        sh[0] = r;
    }
    __syncthreads();
    float r = sh[0];
    __syncthreads();
    return r;
}

// ---------------- GEMM stage loader (48KB: Ah16K,Al16K,Bh8K,Bl8K) ----------------
__device__ __forceinline__ void load_stage(char* st,
  const bf16* Ah, const bf16* Al, const bf16* Bh, const bf16* Bl,
  int lda, int ldb, int k0, int tid)
{
  char* sAh = st; char* sAl = st+16384; char* sBh = st+32768; char* sBl = st+40960;
  int r0 = tid>>3, ch = tid&7;
  #pragma unroll
  for(int e=0;e<4;e++){
    int r = r0 + e*32;
    int off = swz(r, ch*16);
    cpa16(sAh+off, Ah + (size_t)r*lda + k0 + ch*8);
    cpa16(sAl+off, Al + (size_t)r*lda + k0 + ch*8);
  }
  #pragma unroll
  for(int e=0;e<2;e++){
    int r = r0 + e*32;
    int off = swz(r, ch*16);
    cpa16(sBh+off, Bh + (size_t)r*ldb + k0 + ch*8);
    cpa16(sBl+off, Bl + (size_t)r*ldb + k0 + ch*8);
  }
}

__device__ __forceinline__ void compute_stage(char* st, float acc[2][4][4], int lane, int wm, int wn)
{
  char* sAh = st; char* sAl = st+16384; char* sBh = st+32768; char* sBl = st+40960;
  #pragma unroll
  for(int kk=0;kk<4;kk++){
    unsigned Ah[2][4], Al[2][4], Bh[4][2], Bl[4][2];
    #pragma unroll
    for(int mt=0;mt<2;mt++){
      int r = wm + mt*16 + (lane & 15);
      int cb = kk*32 + ((lane >> 4) << 4);
      int off = swz(r, cb);
      ldsm4(Ah[mt][0],Ah[mt][1],Ah[mt][2],Ah[mt][3], su32(sAh + off));
      ldsm4(Al[mt][0],Al[mt][1],Al[mt][2],Al[mt][3], su32(sAl + off));
    }
    #pragma unroll
    for(int p=0;p<2;p++){
      int r = wn + p*16 + (lane & 15);
      int cb = kk*32 + ((lane >> 4) << 4);
      int off = swz(r, cb);
      unsigned r0,r1,r2,r3;
      ldsm4(r0,r1,r2,r3, su32(sBh + off));
      Bh[p*2][0]=r0; Bh[p*2][1]=r2; Bh[p*2+1][0]=r1; Bh[p*2+1][1]=r3;
      ldsm4(r0,r1,r2,r3, su32(sBl + off));
      Bl[p*2][0]=r0; Bl[p*2][1]=r2; Bl[p*2+1][0]=r1; Bl[p*2+1][1]=r3;
    }
    #pragma unroll
    for(int mt=0;mt<2;mt++)
      #pragma unroll
      for(int ns=0;ns<4;ns++){
        mma16816(acc[mt][ns], Ah[mt], Bh[ns][0], Bh[ns][1]);
        mma16816(acc[mt][ns], Ah[mt], Bl[ns][0], Bl[ns][1]);
        mma16816(acc[mt][ns], Al[mt], Bh[ns][0], Bh[ns][1]);
      }
  }
}

// shared 2-stage mainloop
__device__ __forceinline__ void mainloop2(
  float acc[2][4][4], const bf16* Ahp, const bf16* Alp, const bf16* Bhp, const bf16* Blp,
  int lda, int ldb, int nk, int tid, int lane, int wm, int wn, char* st0, char* st1)
{
  load_stage(st0, Ahp, Alp, Bhp, Blp, lda, ldb, 0, tid);
  asm volatile("cp.async.commit_group;\n");
  for(int i=0;i<nk;i++){
    if(i+1 < nk){
      load_stage((i&1)?st0:st1, Ahp, Alp, Bhp, Blp, lda, ldb, (i+1)<<6, tid);
      asm volatile("cp.async.commit_group;\n");
      asm volatile("cp.async.wait_group 1;\n");
    } else {
      asm volatile("cp.async.wait_group 0;\n");
    }
    __syncthreads();
    compute_stage((i&1)?st1:st0, acc, lane, wm, wn);
    __syncthreads();
  }
}

// EPI bits: 1=bias (z==0 slice only), 2=residual fp32 read-add, 4=silu, 8=store bf16 hi/lo, 16=atomicAdd fp32
template<int EPI>
__global__ void __launch_bounds__(256,2) gemm_bf(
  const bf16* Ah, const bf16* Al, const bf16* Bh, const bf16* Bl,
  const float* bias, float* Cf, bf16* Ch, bf16* Cl,
  int M, int N, int K, int lda, int ldb, int ldc)
{
  extern __shared__ char rawsm[];
  char* st0 = rawsm; char* st1 = rawsm + 49152;
  int tid = threadIdx.x, lane = tid&31, warp = tid>>5;
  int wm = (warp>>1)*32, wn = (warp&1)*32;
  int m0 = blockIdx.y*128, n0 = blockIdx.x*64;
  size_t kofs = (size_t)blockIdx.z * K;
  const float* bz = (blockIdx.z == 0) ? bias : nullptr;

  float acc[2][4][4];
  #pragma unroll
  for(int i=0;i<2;i++)
    #pragma unroll
    for(int j=0;j<4;j++)
      #pragma unroll
      for(int e=0;e<4;e++) acc[i][j][e]=0.f;

  mainloop2(acc, Ah + (size_t)m0*lda + kofs, Al + (size_t)m0*lda + kofs,
            Bh + (size_t)n0*ldb + kofs, Bl + (size_t)n0*ldb + kofs,
            lda, ldb, K>>6, tid, lane, wm, wn, st0, st1);

  #pragma unroll
  for(int mt=0;mt<2;mt++)
    #pragma unroll
    for(int ns=0;ns<4;ns++){
      int row = m0 + wm + mt*16 + (lane>>2);
      int col = n0 + wn + ns*8 + (lane&3)*2;
      #pragma unroll
      for(int e=0;e<4;e++){
        int rr = row + ((e>=2)?8:0);
        int cc = col + (e&1);
        if(rr < M && cc < N){
          float v = acc[mt][ns][e];
          if((EPI&1) && bz) v += bz[cc];
          if(EPI&4) v = v/(1.f+expf(-v));
          if(EPI&16){
            atomicAdd(&Cf[(size_t)rr*ldc+cc], v);
          } else if(EPI&8){
            unsigned short h,l; split1(v,h,l);
            Ch[(size_t)rr*ldc+cc] = __ushort_as_bfloat16(h);
            Cl[(size_t)rr*ldc+cc] = __ushort_as_bfloat16(l);
          } else {
            if(EPI&2) v += Cf[(size_t)rr*ldc+cc];
            Cf[(size_t)rr*ldc+cc] = v;
          }
        }
      }
    }
}

// fused QKV: split-K x2 on z in {0,1} -> plain store into per-slice buffer; z in {2..6} converts NEXT layer's gate/up/down
__global__ void __launch_bounds__(256,2) qkv_gemm(
  const bf16* Ah, const bf16* Al,
  const bf16* qwh, const bf16* qwl, const bf16* kwh, const bf16* kwl,
  const bf16* vwh, const bf16* vwl,
  float* qkv, int layer,
  const float* gate_w, const float* up_w, const float* down_w,
  bf16* gwh, bf16* gwl, bf16* uwh, bf16* uwl, bf16* dwh, bf16* dwl)
{
  extern __shared__ char rawsm[];
  if (blockIdx.z >= 2) {
    int nl = layer + 1;
    if (nl < LNUM) {
      int cb = (blockIdx.z - 2)*160 + blockIdx.y*40 + blockIdx.x;
      const int nb = 5*160;
      const int n4 = 4096*1024/4;
      size_t o = (size_t)nl*4096*1024;
      conv_gs(gate_w + o, gwh + o, gwl + o, n4, cb, nb);
      conv_gs(up_w   + o, uwh + o, uwl + o, n4, cb, nb);
      conv_gs(down_w + o, dwh + o, dwl + o, n4, cb, nb);
    }
    return;
  }
  char* st0 = rawsm; char* st1 = rawsm + 49152;
  int bx = blockIdx.x, m0 = blockIdx.y*128;
  size_t kofs = (size_t)blockIdx.z * 512;
  float* C = qkv + (size_t)blockIdx.z * MTOT * QKVLD;
  const bf16 *Bh, *Bl; int n0, cbase;
  if (bx < 32) {
    size_t w = (size_t)layer*2048*1024;
    Bh = qwh + w; Bl = qwl + w; n0 = bx*64; cbase = n0;
  } else if (bx < 36) {
    size_t w = (size_t)layer*256*1024;
    Bh = kwh + w; Bl = kwl + w; n0 = (bx-32)*64; cbase = 2048 + n0;
  } else {
    size_t w = (size_t)layer*256*1024;
    Bh = vwh + w; Bl = vwl + w; n0 = (bx-36)*64; cbase = 2304 + n0;
  }
  int tid = threadIdx.x, lane = tid&31, warp = tid>>5;
  int wm = (warp>>1)*32, wn = (warp&1)*32;

  float acc[2][4][4];
  #pragma unroll
  for(int i=0;i<2;i++)
    #pragma unroll
    for(int j=0;j<4;j++)
      #pragma unroll
      for(int e=0;e<4;e++) acc[i][j][e]=0.f;

  mainloop2(acc, Ah + (size_t)m0*1024 + kofs, Al + (size_t)m0*1024 + kofs,
            Bh + (size_t)n0*1024 + kofs, Bl + (size_t)n0*1024 + kofs,
            1024, 1024, 8, tid, lane, wm, wn, st0, st1);

  #pragma unroll
  for(int mt=0;mt<2;mt++)
    #pragma unroll
    for(int ns=0;ns<4;ns++){
      int row = m0 + wm + mt*16 + (lane>>2);
      int col = cbase + wn + ns*8 + (lane&3)*2;
      #pragma unroll
      for(int e=0;e<4;e++){
        int rr = row + ((e>=2)?8:0);
        int cc = col + (e&1);
        if(rr < MTOT)
          C[(size_t)rr*QKVLD+cc] = acc[mt][ns][e];
      }
    }
}

// fused gate+up+gelu-mul on z==0; z {1,2}: next layer q/k/v/o weights; z {3,4}: next layer KV prefix
__global__ void __launch_bounds__(256,2) gateup_gemm(
  const bf16* Ah, const bf16* Al,
  const bf16* gwh, const bf16* gwl, const bf16* uwh, const bf16* uwl,
  bf16* midh, bf16* midl, int layer,
  const float* q_w, const float* k_w, const float* v_w, const float* o_w,
  bf16* qwh, bf16* qwl, bf16* kwh, bf16* kwl, bf16* vwh, bf16* vwl, bf16* owh, bf16* owl,
  const float* pk, const float* pv, bf16* kvkh, bf16* kvkl, bf16* kvvh, bf16* kvvl)
{
  extern __shared__ char rawsm[];
  if (blockIdx.z >= 3) {
    int nl = layer + 1;
    if (nl < LNUM) {
      int cb = (blockIdx.z - 3)*256 + blockIdx.y*64 + blockIdx.x;
      conv_kvprefix(pk, pv, nl, kvkh, kvkl, kvvh, kvvl, cb, 512);
    }
    return;
  }
  if (blockIdx.z >= 1) {
    int nl = layer + 1;
    if (nl < LNUM) {
      int cb = (blockIdx.z - 1)*256 + blockIdx.y*64 + blockIdx.x;
      const int nb = 2*256;
      size_t oq = (size_t)nl*2048*1024;
      size_t ok = (size_t)nl*256*1024;
      conv_gs(q_w + oq, qwh + oq, qwl + oq, 2048*1024/4, cb, nb);
      conv_gs(k_w + ok, kwh + ok, kwl + ok, 256*1024/4, cb, nb);
      conv_gs(v_w + ok, vwh + ok, vwl + ok, 256*1024/4, cb, nb);
      conv_gs(o_w + oq, owh + oq, owl + oq, 2048*1024/4, cb, nb);
    }
    return;
  }
  char* st0 = rawsm; char* st1 = rawsm + 49152;
  size_t w = (size_t)layer*4096*1024;
  int tid = threadIdx.x, lane = tid&31, warp = tid>>5;
  int wm = (warp>>1)*32, wn = (warp&1)*32;
  int m0 = blockIdx.y*128, n0 = blockIdx.x*64;
  const bf16* Ahp = Ah + (size_t)m0*1024;
  const bf16* Alp = Al + (size_t)m0*1024;

  float acc[2][4][4];
  #pragma unroll
  for(int i=0;i<2;i++)
    #pragma unroll
    for(int j=0;j<4;j++)
      #pragma unroll
      for(int e=0;e<4;e++) acc[i][j][e]=0.f;

  // pass 1: gate
  mainloop2(acc, Ahp, Alp, gwh + w + (size_t)n0*1024, gwl + w + (size_t)n0*1024,
            1024, 1024, 16, tid, lane, wm, wn, st0, st1);

  float accg[2][4][4];
  #pragma unroll
  for(int i=0;i<2;i++)
    #pragma unroll
    for(int j=0;j<4;j++)
      #pragma unroll
      for(int e=0;e<4;e++){
        float g = acc[i][j][e];
        float t = tanhf(0.7978845608028654f * (g + 0.044715f*g*g*g));
        accg[i][j][e] = 0.5f * g * (1.f + t);
        acc[i][j][e] = 0.f;
      }

  // pass 2: up
  mainloop2(acc, Ahp, Alp, uwh + w + (size_t)n0*1024, uwl + w + (size_t)n0*1024,
            1024, 1024, 16, tid, lane, wm, wn, st0, st1);

  #pragma unroll
  for(int mt=0;mt<2;mt++)
    #pragma unroll
    for(int ns=0;ns<4;ns++){
      int row = m0 + wm + mt*16 + (lane>>2);
      int col = n0 + wn + ns*8 + (lane&3)*2;
      #pragma unroll
      for(int e=0;e<4;e++){
        int rr = row + ((e>=2)?8:0);
        int cc = col + (e&1);
        if(rr < MTOT){
          float v = accg[mt][ns][e] * acc[mt][ns][e];
          unsigned short h,l; split1(v,h,l);
          midh[(size_t)rr*4096+cc] = __ushort_as_bfloat16(h);
          midl[(size_t)rr*4096+cc] = __ushort_as_bfloat16(l);
        }
      }
    }
}

// ---------------- weight conversion (upfront: layer 0 + prologue) ----------------
__global__ void convsplit(const float* __restrict__ s, bf16* __restrict__ h, bf16* __restrict__ l, int n4)
{
  int i = blockIdx.x*blockDim.x + threadIdx.x;
  if(i >= n4) return;
  float4 v = ((const float4*)s)[i];
  unsigned short h0,l0,h1,l1,h2,l2,h3,l3;
  split1(v.x,h0,l0); split1(v.y,h1,l1); split1(v.z,h2,l2); split1(v.w,h3,l3);
  ((uint2*)h)[i] = make_uint2((unsigned)h0|((unsigned)h1<<16), (unsigned)h2|((unsigned)h3<<16));
  ((uint2*)l)[i] = make_uint2((unsigned)l0|((unsigned)l1<<16), (unsigned)l2|((unsigned)l3<<16));
}

__global__ void padconv32(const float* __restrict__ s, bf16* __restrict__ h, bf16* __restrict__ l, int rows)
{
  int i = blockIdx.x*blockDim.x + threadIdx.x;
  if(i >= rows*32) return;
  int r = i >> 5, c = i & 31;
  unsigned short hh, ll;
  split1(s[i], hh, ll);
  h[r*64+c] = __ushort_as_bfloat16(hh);
  l[r*64+c] = __ushort_as_bfloat16(ll);
}

// ---------------- silu + bf16 split ----------------
__global__ void silu_split(const float* __restrict__ in, bf16* __restrict__ oh, bf16* __restrict__ ol, int n)
{
  int i = blockIdx.x*blockDim.x + threadIdx.x;
  if (i >= n) return;
  float v = in[i];
  v = v/(1.f+expf(-v));
  unsigned short h, l;
  split1(v, h, l);
  oh[i] = __ushort_as_bfloat16(h);
  ol[i] = __ushort_as_bfloat16(l);
}

// ---------------- attention scores: head-pair blocks ----------------
__global__ void __launch_bounds__(256,2) attn_scores(
  const bf16* __restrict__ qh, const bf16* __restrict__ ql,
  const bf16* __restrict__ kh, const bf16* __restrict__ kl,
  float* __restrict__ S)
{
  extern __shared__ char rawsm[];
  char* st0 = rawsm; char* st1 = rawsm + 49152;
  int t0 = blockIdx.x * 64;
  int bp = blockIdx.y;
  int b = bp >> 2, hp = bp & 3;
  int zbase = b*NHH + hp*2;
  int tid = threadIdx.x, lane = tid&31, warp = tid>>5;
  int wm = (warp>>1)*32, wn = (warp&1)*32;

  float acc[2][4][4];
  #pragma unroll
  for(int i=0;i<2;i++)
    #pragma unroll
    for(int j=0;j<4;j++)
      #pragma unroll
      for(int e=0;e<4;e++) acc[i][j][e]=0.f;

  mainloop2(acc, qh + (size_t)zbase*CP*HD, ql + (size_t)zbase*CP*HD,
            kh + ((size_t)b*TP + t0)*HD, kl + ((size_t)b*TP + t0)*HD,
            HD, HD, HD/64, tid, lane, wm, wn, st0, st1);

  float* Sb = S + (size_t)zbase*CP*TP;
  #pragma unroll
  for(int mt=0;mt<2;mt++)
    #pragma unroll
    for(int ns=0;ns<4;ns++){
      int row = wm + mt*16 + (lane>>2);
      int col = t0 + wn + ns*8 + (lane&3)*2;
      Sb[(size_t)row*TP + col]          = acc[mt][ns][0];
      Sb[(size_t)row*TP + col + 1]      = acc[mt][ns][1];
      Sb[(size_t)(row+8)*TP + col]      = acc[mt][ns][2];
      Sb[(size_t)(row+8)*TP + col + 1]  = acc[mt][ns][3];
    }
}

// ---------------- attention AV: head-pair blocks, trans-B V ----------------
__device__ __forceinline__ void av_load(char* st,
  const bf16* Agh, const bf16* Agl, const bf16* Bgh, const bf16* Bgl, int k0, int tid)
{
  char* sAh = st; char* sAl = st+16384; char* sBh = st+32768; char* sBl = st+40960;
  int r0 = tid>>3, ch = tid&7;
  #pragma unroll
  for(int e=0;e<4;e++){
    int r = r0 + e*32;
    int off = swz(r, ch*16);
    cpa16(sAh+off, Agh + (size_t)r*TP + k0 + ch*8);
    cpa16(sAl+off, Agl + (size_t)r*TP + k0 + ch*8);
  }
  #pragma unroll
  for(int e=0;e<2;e++){
    int r = r0 + e*32;
    int off = swz(r, ch*16);
    cpa16(sBh+off, Bgh + (size_t)(k0 + r)*HD + ch*8);
    cpa16(sBl+off, Bgl + (size_t)(k0 + r)*HD + ch*8);
  }
}

__device__ __forceinline__ void av_compute(char* st, float acc[2][4][4], int lane, int wm, int wn)
{
  char* sAh = st; char* sAl = st+16384; char* sBh = st+32768; char* sBl = st+40960;
  #pragma unroll
  for(int kk=0;kk<4;kk++){
    unsigned Ah[2][4], Al[2][4], Bh[4][2], Bl[4][2];
    #pragma unroll
    for(int mt=0;mt<2;mt++){
      int r = wm + mt*16 + (lane & 15);
      int cb = kk*32 + ((lane >> 4) << 4);
      int off = swz(r, cb);
      ldsm4(Ah[mt][0],Ah[mt][1],Ah[mt][2],Ah[mt][3], su32(sAh + off));
      ldsm4(Al[mt][0],Al[mt][1],Al[mt][2],Al[mt][3], su32(sAl + off));
    }
    #pragma unroll
    for(int p=0;p<2;p++){
      int r = kk*16 + (lane & 15);
      int cb = (wn + p*16)*2 + ((lane >> 4) << 4);
      int off = swz(r, cb);
      unsigned r0,r1,r2,r3;
      ldsm4t(r0,r1,r2,r3, su32(sBh + off));
      Bh[p*2][0]=r0; Bh[p*2][1]=r1; Bh[p*2+1][0]=r2; Bh[p*2+1][1]=r3;
      ldsm4t(r0,r1,r2,r3, su32(sBl + off));
      Bl[p*2][0]=r0; Bl[p*2][1]=r1; Bl[p*2+1][0]=r2; Bl[p*2+1][1]=r3;
    }
    #pragma unroll
    for(int mt=0;mt<2;mt++)
      #pragma unroll
      for(int ns=0;ns<4;ns++){
        mma16816(acc[mt][ns], Ah[mt], Bh[ns][0], Bh[ns][1]);
        mma16816(acc[mt][ns], Ah[mt], Bl[ns][0], Bl[ns][1]);
        mma16816(acc[mt][ns], Al[mt], Bh[ns][0], Bh[ns][1]);
      }
  }
}

__global__ void __launch_bounds__(256,2) attn_av(
  const bf16* __restrict__ sh_, const bf16* __restrict__ sl_,
  const bf16* __restrict__ vh, const bf16* __restrict__ vl,
  bf16* __restrict__ Oh, bf16* __restrict__ Ol)
{
  extern __shared__ char rawsm[];
  char* st0 = rawsm; char* st1 = rawsm + 49152;
  int d0 = blockIdx.x * 64;
  int bp = blockIdx.y;
  int b = bp >> 2, hp = bp & 3;
  int zbase = b*NHH + hp*2;
  int tid = threadIdx.x, lane = tid&31, warp = tid>>5;
  int wm = (warp>>1)*32, wn = (warp&1)*32;
  const bf16* Agh = sh_ + (size_t)zbase*CP*TP;
  const bf16* Agl = sl_ + (size_t)zbase*CP*TP;
  const bf16* Bgh = vh + (size_t)b*TP*HD + d0;
  const bf16* Bgl = vl + (size_t)b*TP*HD + d0;

  float acc[2][4][4];
  #pragma unroll
  for(int i=0;i<2;i++)
    #pragma unroll
    for(int j=0;j<4;j++)
      #pragma unroll
      for(int e=0;e<4;e++) acc[i][j][e]=0.f;

  const int nk = TP/64;  // 14
  av_load(st0, Agh, Agl, Bgh, Bgl, 0, tid);
  asm volatile("cp.async.commit_group;\n");
  for(int i=0;i<nk;i++){
    if(i+1 < nk){
      av_load((i&1)?st0:st1, Agh, Agl, Bgh, Bgl, (i+1)<<6, tid);
      asm volatile("cp.async.commit_group;\n");
      asm volatile("cp.async.wait_group 1;\n");
    } else {
      asm volatile("cp.async.wait_group 0;\n");
    }
    __syncthreads();
    av_compute((i&1)?st1:st0, acc, lane, wm, wn);
    __syncthreads();
  }

  #pragma unroll
  for(int mt=0;mt<2;mt++)
    #pragma unroll
    for(int ns=0;ns<4;ns++){
      int row = wm + mt*16 + (lane>>2);
      int d = d0 + wn + ns*8 + (lane&3)*2;
      #pragma unroll
      for(int e=0;e<4;e++){
        int rr = row + ((e>=2)?8:0);
        int dd = d + (e&1);
        int hd2 = hp*2 + (rr>>6);
        int c = rr & 63;
        if(c < CC){
          unsigned short h, l;
          split1(acc[mt][ns][e], h, l);
          size_t idx = ((size_t)(b*CC + c))*(NHH*HD) + hd2*HD + dd;
          Oh[idx] = __ushort_as_bfloat16(h);
          Ol[idx] = __ushort_as_bfloat16(l);
        }
      }
    }
}

__global__ void __launch_bounds__(256) softmax_kernel(
  const float* __restrict__ S, bf16* __restrict__ Sh, bf16* __restrict__ Sl)
{
  int row = blockIdx.x;
  int z = row / CC, c = row % CC;
  const float* s = S + ((size_t)z*CP + c)*TP;
  float vals[4];
  float mx = -1e30f;
  #pragma unroll
  for (int ii = 0; ii < 4; ii++) {
    int j = threadIdx.x + ii*256;
    vals[ii] = (j < TTOT) ? s[j] : -1e30f;
    mx = fmaxf(mx, vals[ii]);
  }
  mx = blk_reduce(mx, true);
  float sum = 0.f;
  #pragma unroll
  for (int ii = 0; ii < 4; ii++) {
    int j = threadIdx.x + ii*256;
    if (j < TTOT) { vals[ii] = expf(vals[ii] - mx); sum += vals[ii]; }
  }
  sum = blk_reduce(sum, false);
  float inv = 1.f / sum;
  size_t base = ((size_t)z*CP + c)*TP;
  #pragma unroll
  for (int ii = 0; ii < 4; ii++) {
    int j = threadIdx.x + ii*256;
    if (j < TTOT) {
      float p = vals[ii] * inv;
      unsigned short h, l;
      split1(p, h, l);
      Sh[base + j] = __ushort_as_bfloat16(h);
      Sl[base + j] = __ushort_as_bfloat16(l);
    }
  }
}

// ---------------- new-token q/k/v rope + split (prefix handled by prefetch) ----------------
__global__ void qkvconv_kernel(
  const float* __restrict__ qkv, const int* __restrict__ pos,
  bf16* __restrict__ qh, bf16* __restrict__ ql,
  bf16* __restrict__ kh, bf16* __restrict__ kl,
  bf16* __restrict__ vh, bf16* __restrict__ vl)
{
  const float* qkv1 = qkv + (size_t)MTOT*QKVLD;
  int idx = blockIdx.x * blockDim.x + threadIdx.x;
  unsigned short h, l;
  if (idx < NQ_ITEMS) {
    int i = idx & 127;
    int mn = idx >> 7;
    int n = mn & 7, m = mn >> 3;
    int b = m / CC, c = m % CC;
    size_t po = (size_t)m*QKVLD + n*HD;
    float x1 = qkv[po + i] + qkv1[po + i];
    float x2 = qkv[po + i + 128] + qkv1[po + i + 128];
    float ang = (float)pos[c] * expf(-(float)i * (9.210340371976184f/128.f));
    float sn, cs; sincosf(ang, &sn, &cs);
    float o1 = (x1*cs - x2*sn) * 0.0625f;
    float o2 = (x2*cs + x1*sn) * 0.0625f;
    size_t dst = ((size_t)(b*NHH + n)*CP + c)*HD;
    split1(o1, h, l); qh[dst+i] = __ushort_as_bfloat16(h); ql[dst+i] = __ushort_as_bfloat16(l);
    split1(o2, h, l); qh[dst+i+128] = __ushort_as_bfloat16(h); ql[dst+i+128] = __ushort_as_bfloat16(l);
  } else if (idx < NQ_ITEMS + NKNEW_ITEMS) {
    int j = idx - NQ_ITEMS;
    int d = j & 127;
    int bc = j >> 7;
    int c = bc % CC, b = bc / CC;
    size_t po = (size_t)(b*CC + c)*QKVLD + 2048;
    float x1 = qkv[po + d] + qkv1[po + d];
    float x2 = qkv[po + d + 128] + qkv1[po + d + 128];
    float ang = (float)pos[c] * expf(-(float)d * (9.210340371976184f/128.f));
    float sn, cs; sincosf(ang, &sn, &cs);
    float o1 = x1*cs - x2*sn;
    float o2 = x2*cs + x1*sn;
    size_t dst = ((size_t)b*TP + PP + c)*HD;
    split1(o1, h, l); kh[dst+d] = __ushort_as_bfloat16(h); kl[dst+d] = __ushort_as_bfloat16(l);
    split1(o2, h, l); kh[dst+d+128] = __ushort_as_bfloat16(h); kl[dst+d+128] = __ushort_as_bfloat16(l);
  } else if (idx < NQ_ITEMS + NKNEW_ITEMS + NVNEW_ITEMS) {
    int j = idx - NQ_ITEMS - NKNEW_ITEMS;
    int d = j & 255;
    int bc = j >> 8;
    int c = bc % CC, b = bc / CC;
    size_t po = (size_t)(b*CC + c)*QKVLD + 2304 + d;
    float x = qkv[po] + qkv1[po];
    split1(x, h, l);
    size_t dst = ((size_t)b*TP + PP + c)*HD;
    vh[dst+d] = __ushort_as_bfloat16(h);
    vl[dst+d] = __ushort_as_bfloat16(l);
  }
}

// ---------------- other elementwise ----------------
__global__ void __launch_bounds__(256) rmsnorm_bf(
  const float* __restrict__ x, const float* __restrict__ w,
  bf16* __restrict__ oh, bf16* __restrict__ ol)
{
  int row = blockIdx.x;
  const float* xr = x + (size_t)row*HH;
  float ss = 0.f;
  for (int j = threadIdx.x; j < HH; j += 256) { float v = xr[j]; ss += v*v; }
  ss = blk_reduce(ss, false);
  float sc = rsqrtf(ss * (1.f/HH) + 1e-6f);
  for (int j = threadIdx.x; j < HH; j += 256) {
    float v = xr[j] * sc * w[j];
    unsigned short h, l;
    split1(v, h, l);
    oh[(size_t)row*HH + j] = __ushort_as_bfloat16(h);
    ol[(size_t)row*HH + j] = __ushort_as_bfloat16(l);
  }
}

__global__ void timeemb_bf(const float* __restrict__ ts, bf16* __restrict__ xth, bf16* __restrict__ xtl)
{
  int idx = blockIdx.x * blockDim.x + threadIdx.x;
  if (idx >= MTOT*HH) return;
  int m = idx >> 10, j = idx & 1023;
  int b = m / CC;
  float t = ts[b];
  int i = (j < 512) ? j : (j - 512);
  float period = 4e-3f * expf((float)i * (6.907755278982137f/512.f));
  float ang = 6.283185307179586f * t / period;
  float v = (j < 512) ? sinf(ang) : cosf(ang);
  unsigned short h, l;
  split1(v, h, l);
  size_t dst = (size_t)m*(2*HH) + HH + j;
  xth[dst] = __ushort_as_bfloat16(h);
  xtl[dst] = __ushort_as_bfloat16(l);
}

// ---------------- orchestration ----------------
extern "C" void kernel_launch(void* const* d_in, const int* in_sizes, int n_in,
                              void* d_out, int out_size)
{
  const float* noisy   = (const float*)d_in[0];
  const float* tstep   = (const float*)d_in[1];
  const int*   pos_ids = (const int*)d_in[2];
  const float* pk      = (const float*)d_in[3];
  const float* pv      = (const float*)d_in[4];
  const float* in_w    = (const float*)d_in[5];
  const float* in_b    = (const float*)d_in[6];
  const float* t_in_w  = (const float*)d_in[7];
  const float* t_in_b  = (const float*)d_in[8];
  const float* t_out_w = (const float*)d_in[9];
  const float* t_out_b = (const float*)d_in[10];
  const float* out_w   = (const float*)d_in[11];
  const float* out_b   = (const float*)d_in[12];
  const float* fn_w    = (const float*)d_in[13];
  const float* ln1_w   = (const float*)d_in[14];
  const float* q_w     = (const float*)d_in[15];
  const float* k_w     = (const float*)d_in[16];
  const float* v_w     = (const float*)d_in[17];
  const float* o_w     = (const float*)d_in[18];
  const float* ln2_w   = (const float*)d_in[19];
  const float* gate_w  = (const float*)d_in[20];
  const float* up_w    = (const float*)d_in[21];
  const float* down_w  = (const float*)d_in[22];
  float* out = (float*)d_out;

  float *x,*qkv,*s,*gate;
  bf16 *hh,*hl,*xth,*xtl,*midh,*midl,*aoh,*aol,*nh,*nl;
  bf16 *qh,*ql,*kh,*kl,*vh,*vl,*sh,*sl;
  bf16 *qwh,*qwl,*kwh,*kwl,*vwh,*vwl,*owh,*owl,*gwh,*gwl,*uwh,*uwl,*dwh,*dwl;
  bf16 *tinh,*tinl,*touth,*toutl,*outwh,*outwl,*inwh,*inwl;

  cudaGetSymbolAddress((void**)&x, g_x);
  cudaGetSymbolAddress((void**)&qkv, g_qkv);
  cudaGetSymbolAddress((void**)&s, g_s);
  cudaGetSymbolAddress((void**)&gate, g_gate);
  cudaGetSymbolAddress((void**)&hh, g_hh);   cudaGetSymbolAddress((void**)&hl, g_hl);
  cudaGetSymbolAddress((void**)&xth, g_xth); cudaGetSymbolAddress((void**)&xtl, g_xtl);
  cudaGetSymbolAddress((void**)&midh, g_midh); cudaGetSymbolAddress((void**)&midl, g_midl);
  cudaGetSymbolAddress((void**)&aoh, g_aoh); cudaGetSymbolAddress((void**)&aol, g_aol);
  cudaGetSymbolAddress((void**)&nh, g_nh);   cudaGetSymbolAddress((void**)&nl, g_nl);
  cudaGetSymbolAddress((void**)&qh, g_qh);   cudaGetSymbolAddress((void**)&ql, g_ql);
  cudaGetSymbolAddress((void**)&kh, g_kh);   cudaGetSymbolAddress((void**)&kl, g_kl);
  cudaGetSymbolAddress((void**)&vh, g_vh);   cudaGetSymbolAddress((void**)&vl, g_vl);
  cudaGetSymbolAddress((void**)&sh, g_sh);   cudaGetSymbolAddress((void**)&sl, g_sl);
  cudaGetSymbolAddress((void**)&qwh, g_qwh); cudaGetSymbolAddress((void**)&qwl, g_qwl);
  cudaGetSymbolAddress((void**)&kwh, g_kwh); cudaGetSymbolAddress((void**)&kwl, g_kwl);
  cudaGetSymbolAddress((void**)&vwh, g_vwh); cudaGetSymbolAddress((void**)&vwl, g_vwl);
  cudaGetSymbolAddress((void**)&owh, g_owh); cudaGetSymbolAddress((void**)&owl, g_owl);
  cudaGetSymbolAddress((void**)&gwh, g_gwh); cudaGetSymbolAddress((void**)&gwl, g_gwl);
  cudaGetSymbolAddress((void**)&uwh, g_uwh); cudaGetSymbolAddress((void**)&uwl, g_uwl);
  cudaGetSymbolAddress((void**)&dwh, g_dwh); cudaGetSymbolAddress((void**)&dwl, g_dwl);
  cudaGetSymbolAddress((void**)&tinh, g_tinh);   cudaGetSymbolAddress((void**)&tinl, g_tinl);
  cudaGetSymbolAddress((void**)&touth, g_touth); cudaGetSymbolAddress((void**)&toutl, g_toutl);
  cudaGetSymbolAddress((void**)&outwh, g_outwh); cudaGetSymbolAddress((void**)&outwl, g_outwl);
  cudaGetSymbolAddress((void**)&inwh, g_inwh);   cudaGetSymbolAddress((void**)&inwl, g_inwl);

  cudaFuncSetAttribute(gemm_bf<9>,  cudaFuncAttributeMaxDynamicSharedMemorySize, SMEM_GEMM);
  cudaFuncSetAttribute(gemm_bf<17>, cudaFuncAttributeMaxDynamicSharedMemorySize, SMEM_GEMM);
  cudaFuncSetAttribute(gemm_bf<18>, cudaFuncAttributeMaxDynamicSharedMemorySize, SMEM_GEMM);
  cudaFuncSetAttribute(qkv_gemm,    cudaFuncAttributeMaxDynamicSharedMemorySize, SMEM_GEMM);
  cudaFuncSetAttribute(gateup_gemm, cudaFuncAttributeMaxDynamicSharedMemorySize, SMEM_GEMM);
  cudaFuncSetAttribute(attn_scores, cudaFuncAttributeMaxDynamicSharedMemorySize, SMEM_GEMM);
  cudaFuncSetAttribute(attn_av,     cudaFuncAttributeMaxDynamicSharedMemorySize, SMEM_GEMM);

  // ---- upfront conversion: layer 0 + prologue weights + layer-0 KV prefix ----
  {
    int n;
    n = 2048*1024/4;  convsplit<<<(n+255)/256,256>>>(q_w, qwh, qwl, n);
    n = 256*1024/4;   convsplit<<<(n+255)/256,256>>>(k_w, kwh, kwl, n);
    n = 256*1024/4;   convsplit<<<(n+255)/256,256>>>(v_w, vwh, vwl, n);
    n = 1024*2048/4;  convsplit<<<(n+255)/256,256>>>(o_w, owh, owl, n);
    n = 4096*1024/4;  convsplit<<<(n+255)/256,256>>>(gate_w, gwh, gwl, n);
    n = 4096*1024/4;  convsplit<<<(n+255)/256,256>>>(up_w, uwh, uwl, n);
    n = 1024*4096/4;  convsplit<<<(n+255)/256,256>>>(down_w, dwh, dwl, n);
    n = 1024*2048/4;  convsplit<<<(n+255)/256,256>>>(t_in_w, tinh, tinl, n);
    n = 1024*1024/4;  convsplit<<<(n+255)/256,256>>>(t_out_w, touth, toutl, n);
    n = 32*1024/4;    convsplit<<<(n+255)/256,256>>>(out_w, outwh, outwl, n);
    padconv32<<<(1024*32+255)/256,256>>>(in_w, inwh, inwl, 1024);
    padconv32<<<(MTOT*32+255)/256,256>>>(noisy, nh, nl, MTOT);
    kvprefix_kernel<<<512,256>>>(pk, pv, 0, kh, kl, vh, vl);
  }

  // ---- prologue ----
  gemm_bf<9><<<dim3(16,4,1),256,SMEM_GEMM>>>(nh, nl, inwh, inwl, in_b, nullptr, xth, xtl,
                                             MTOT, 1024, 64, 64, 64, 2048);
  timeemb_bf<<<(MTOT*HH+255)/256,256>>>(tstep, xth, xtl);
  cudaMemsetAsync(gate, 0, (size_t)MTOT*HH*sizeof(float));
  gemm_bf<17><<<dim3(16,4,2),256,SMEM_GEMM>>>(xth, xtl, tinh, tinl, t_in_b, gate, nullptr, nullptr,
                                              MTOT, 1024, 1024, 2048, 2048, 1024);
  silu_split<<<(MTOT*1024+255)/256,256>>>(gate, hh, hl, MTOT*1024);
  cudaMemsetAsync(x, 0, (size_t)MTOT*HH*sizeof(float));
  gemm_bf<17><<<dim3(16,4,2),256,SMEM_GEMM>>>(hh, hl, touth, toutl, t_out_b, x, nullptr, nullptr,
                                              MTOT, 1024, 512, 1024, 1024, 1024);

  int convgrid = (NQ_ITEMS + NKNEW_ITEMS + NVNEW_ITEMS + 255)/256;
  for (int l = 0; l < LNUM; l++) {
    bf16* khl = kh + (size_t)(l&1)*KVSTRIDE;
    bf16* kll = kl + (size_t)(l&1)*KVSTRIDE;
    bf16* vhl = vh + (size_t)(l&1)*KVSTRIDE;
    bf16* vll = vl + (size_t)(l&1)*KVSTRIDE;

    rmsnorm_bf<<<MTOT,256>>>(x, ln1_w + l*HH, hh, hl);
    // z 0..1: QKV GEMM; z 2..6: convert layer l+1 gate/up/down weights
    qkv_gemm<<<dim3(40,4,7),256,SMEM_GEMM>>>(hh, hl, qwh, qwl, kwh, kwl, vwh, vwl, qkv, l,
                                             gate_w, up_w, down_w, gwh, gwl, uwh, uwl, dwh, dwl);
    qkvconv_kernel<<<convgrid,256>>>(qkv, pos_ids, qh, ql, khl, kll, vhl, vll);
    attn_scores<<<dim3(TP/64, BB*4),256,SMEM_GEMM>>>(qh, ql, khl, kll, s);
    softmax_kernel<<<BB*NHH*CC,256>>>(s, sh, sl);
    attn_av<<<dim3(HD/64, BB*4),256,SMEM_GEMM>>>(sh, sl, vhl, vll, aoh, aol);
    gemm_bf<18><<<dim3(16,4,4),256,SMEM_GEMM>>>(aoh, aol,
        owh + (size_t)l*1024*2048, owl + (size_t)l*1024*2048,
        nullptr, x, nullptr, nullptr, MTOT, 1024, 512, 2048, 2048, 1024);
    rmsnorm_bf<<<MTOT,256>>>(x, ln2_w + l*HH, hh, hl);
    // z 0: fused gate+up+gelu-mul GEMM; z 1..2: layer l+1 q/k/v/o weights; z 3..4: layer l+1 KV prefix
    gateup_gemm<<<dim3(64,4,5),256,SMEM_GEMM>>>(hh, hl, gwh, gwl, uwh, uwl, midh, midl, l,
                                                q_w, k_w, v_w, o_w,
                                                qwh, qwl, kwh, kwl, vwh, vwl, owh, owl,
                                                pk, pv, kh, kl, vh, vl);
    gemm_bf<18><<<dim3(16,4,4),256,SMEM_GEMM>>>(midh, midl,
        dwh + (size_t)l*1024*4096, dwl + (size_t)l*1024*4096,
        nullptr, x, nullptr, nullptr, MTOT, 1024, 1024, 4096, 4096, 1024);
  }

  rmsnorm_bf<<<MTOT,256>>>(x, fn_w, hh, hl);
  cudaMemsetAsync(out, 0, (size_t)MTOT*AA*sizeof(float));
  gemm_bf<17><<<dim3(1,4,8),256,SMEM_GEMM>>>(hh, hl, outwh, outwl, out_b, out, nullptr, nullptr,
                                             MTOT, 32, 128, 1024, 1024, 32);
}

// round 16
// speedup vs baseline: 1.0135x; 1.0135x over previous
#include <cuda_runtime.h>
#include <cuda_bf16.h>
#include <cstdint>

#define LNUM 18
#define BB 8
#define CC 50
#define AA 32
#define HH 1024
#define NHH 8
#define HD 256
#define PP 800
#define MLPD 4096
#define MTOT 400
#define TTOT 850
#define TP 896
#define CP 64
#define MPAD 512
#define QKVLD 2560
#define SMEM_GEMM (96*1024)
#define KVSTRIDE (BB*TP*HD)
#define NQ_ITEMS (MTOT*NHH*128)
#define NKNEW_ITEMS (BB*CC*128)
#define NVNEW_ITEMS (BB*CC*HD)

typedef __nv_bfloat16 bf16;

// ---------------- fp32 scratch ----------------
__device__ __align__(256) float g_x[MTOT*HH];
__device__ __align__(256) float g_qkv[2*MTOT*QKVLD];
__device__ __align__(256) float g_s[BB*NHH*CP*TP];
__device__ __align__(256) float g_gate[MTOT*MLPD];
__device__ __align__(256) float g_up[MTOT*MLPD];

// ---------------- bf16 activations (hi/lo) ----------------
__device__ __align__(256) bf16 g_hh[MPAD*HH];
__device__ __align__(256) bf16 g_hl[MPAD*HH];
__device__ __align__(256) bf16 g_xth[MPAD*2*HH];
__device__ __align__(256) bf16 g_xtl[MPAD*2*HH];
__device__ __align__(256) bf16 g_midh[MPAD*MLPD];
__device__ __align__(256) bf16 g_midl[MPAD*MLPD];
__device__ __align__(256) bf16 g_aoh[MPAD*NHH*HD];
__device__ __align__(256) bf16 g_aol[MPAD*NHH*HD];
__device__ __align__(256) bf16 g_nh[MPAD*64];
__device__ __align__(256) bf16 g_nl[MPAD*64];

// ---------------- bf16 attention operands (KV double-buffered by layer parity) ----------------
__device__ __align__(256) bf16 g_qh[BB*NHH*CP*HD];
__device__ __align__(256) bf16 g_ql[BB*NHH*CP*HD];
__device__ __align__(256) bf16 g_kh[2*KVSTRIDE];
__device__ __align__(256) bf16 g_kl[2*KVSTRIDE];
__device__ __align__(256) bf16 g_vh[2*KVSTRIDE];
__device__ __align__(256) bf16 g_vl[2*KVSTRIDE];
__device__ __align__(256) bf16 g_sh[BB*NHH*CP*TP];
__device__ __align__(256) bf16 g_sl[BB*NHH*CP*TP];

// ---------------- bf16 weights (hi/lo) ----------------
__device__ bf16 g_qwh[LNUM*2048*1024];
__device__ bf16 g_qwl[LNUM*2048*1024];
__device__ bf16 g_kwh[LNUM*256*1024];
__device__ bf16 g_kwl[LNUM*256*1024];
__device__ bf16 g_vwh[LNUM*256*1024];
__device__ bf16 g_vwl[LNUM*256*1024];
__device__ bf16 g_owh[LNUM*1024*2048];
__device__ bf16 g_owl[LNUM*1024*2048];
__device__ bf16 g_gwh[LNUM*4096*1024];
__device__ bf16 g_gwl[LNUM*4096*1024];
__device__ bf16 g_uwh[LNUM*4096*1024];
__device__ bf16 g_uwl[LNUM*4096*1024];
__device__ bf16 g_dwh[LNUM*1024*4096];
__device__ bf16 g_dwl[LNUM*1024*4096];
__device__ bf16 g_tinh[1024*2048];
__device__ bf16 g_tinl[1024*2048];
__device__ bf16 g_touth[1024*1024];
__device__ bf16 g_toutl[1024*1024];
__device__ bf16 g_outwh[64*1024];
__device__ bf16 g_outwl[64*1024];
__device__ bf16 g_inwh[1024*64];
__device__ bf16 g_inwl[1024*64];

// ---------------- helpers ----------------
__device__ __forceinline__ unsigned su32(const void* p){ return (unsigned)__cvta_generic_to_shared(p); }
__device__ __forceinline__ int swz(int r, int cb){ return r*128 + (cb ^ ((r&7)<<4)); }

__device__ __forceinline__ void ldsm4(unsigned& a,unsigned& b,unsigned& c,unsigned& d, unsigned addr){
  asm volatile("ldmatrix.sync.aligned.m8n8.x4.shared.b16 {%0,%1,%2,%3},[%4];"
    :"=r"(a),"=r"(b),"=r"(c),"=r"(d):"r"(addr));
}
__device__ __forceinline__ void ldsm4t(unsigned& a,unsigned& b,unsigned& c,unsigned& d, unsigned addr){
  asm volatile("ldmatrix.sync.aligned.m8n8.x4.trans.shared.b16 {%0,%1,%2,%3},[%4];"
    :"=r"(a),"=r"(b),"=r"(c),"=r"(d):"r"(addr));
}
__device__ __forceinline__ void mma16816(float* c, const unsigned* a, unsigned b0, unsigned b1){
  asm volatile("mma.sync.aligned.m16n8k16.row.col.f32.bf16.bf16.f32 {%0,%1,%2,%3},{%4,%5,%6,%7},{%8,%9},{%0,%1,%2,%3};"
    :"+f"(c[0]),"+f"(c[1]),"+f"(c[2]),"+f"(c[3])
    :"r"(a[0]),"r"(a[1]),"r"(a[2]),"r"(a[3]),"r"(b0),"r"(b1));
}
__device__ __forceinline__ void split1(float x, unsigned short& h, unsigned short& l){
  __nv_bfloat16 bh = __float2bfloat16_rn(x);
  h = __bfloat16_as_ushort(bh);
  l = __bfloat16_as_ushort(__float2bfloat16_rn(x - __bfloat162float(bh)));
}
__device__ __forceinline__ void cpa16(void* sdst, const void* gsrc){
  unsigned d = su32(sdst);
  asm volatile("cp.async.cg.shared.global [%0],[%1],16;" :: "r"(d),"l"(gsrc));
}

// grid-stride fp32 -> bf16 hi/lo conversion over n4 float4 elements
__device__ __forceinline__ void conv_gs(const float* __restrict__ src,
  bf16* __restrict__ h, bf16* __restrict__ l, int n4, int cb, int nb)
{
  for (int i = cb*256 + (int)threadIdx.x; i < n4; i += nb*256) {
    float4 v = ((const float4*)src)[i];
    unsigned short h0,l0,h1,l1,h2,l2,h3,l3;
    split1(v.x,h0,l0); split1(v.y,h1,l1); split1(v.z,h2,l2); split1(v.w,h3,l3);
    ((uint2*)h)[i] = make_uint2((unsigned)h0|((unsigned)h1<<16), (unsigned)h2|((unsigned)h3<<16));
    ((uint2*)l)[i] = make_uint2((unsigned)l0|((unsigned)l1<<16), (unsigned)l2|((unsigned)l3<<16));
  }
}

// grid-stride 32->64 padded conversion (rows x 32 fp32 -> rows x 64 bf16 hi/lo)
__device__ __forceinline__ void pad_gs(const float* __restrict__ s,
  bf16* __restrict__ h, bf16* __restrict__ l, int rows, int cb, int nb)
{
  for (int i = cb*256 + (int)threadIdx.x; i < rows*32; i += nb*256) {
    int r = i >> 5, c = i & 31;
    unsigned short hh, ll;
    split1(s[i], hh, ll);
    h[r*64+c] = __ushort_as_bfloat16(hh);
    l[r*64+c] = __ushort_as_bfloat16(ll);
  }
}

// KV prefix conversion for layer nl into parity buffer (nl&1)
__device__ __forceinline__ void conv_kvprefix(const float* __restrict__ pk, const float* __restrict__ pv,
  int nl, bf16* kh, bf16* kl, bf16* vh, bf16* vl, int cb, int nb)
{
  const int n4 = BB*PP*HD/4;
  const float* srcK = pk + (size_t)nl*BB*PP*HD;
  const float* srcV = pv + (size_t)nl*BB*PP*HD;
  size_t bo = (size_t)(nl&1)*KVSTRIDE;
  bf16* dkh = kh + bo; bf16* dkl = kl + bo;
  bf16* dvh = vh + bo; bf16* dvl = vl + bo;
  for (int i = cb*256 + (int)threadIdx.x; i < n4; i += nb*256) {
    int e0 = i*4;
    int d = e0 & 255;
    int bt = e0 >> 8;
    int t = bt % PP, b = bt / PP;
    size_t dst = ((size_t)b*TP + t)*HD + d;
    unsigned short h0,l0,h1,l1,h2,l2,h3,l3;
    float4 v = ((const float4*)srcK)[i];
    split1(v.x,h0,l0); split1(v.y,h1,l1); split1(v.z,h2,l2); split1(v.w,h3,l3);
    *(uint2*)(dkh+dst) = make_uint2((unsigned)h0|((unsigned)h1<<16), (unsigned)h2|((unsigned)h3<<16));
    *(uint2*)(dkl+dst) = make_uint2((unsigned)l0|((unsigned)l1<<16), (unsigned)l2|((unsigned)l3<<16));
    v = ((const float4*)srcV)[i];
    split1(v.x,h0,l0); split1(v.y,h1,l1); split1(v.z,h2,l2); split1(v.w,h3,l3);
    *(uint2*)(dvh+dst) = make_uint2((unsigned)h0|((unsigned)h1<<16), (unsigned)h2|((unsigned)h3<<16));
    *(uint2*)(dvl+dst) = make_uint2((unsigned)l0|((unsigned)l1<<16), (unsigned)l2|((unsigned)l3<<16));
  }
}

// ONE upfront kernel: layer-0 + prologue weights, padded inputs, layer-0 KV prefix
__global__ void convall(
  const float* q_w, const float* k_w, const float* v_w, const float* o_w,
  const float* gate_w, const float* up_w, const float* down_w,
  const float* t_in_w, const float* t_out_w, const float* out_w,
  const float* in_w, const float* noisy, const float* pk, const float* pv,
  bf16* qwh, bf16* qwl, bf16* kwh, bf16* kwl, bf16* vwh, bf16* vwl,
  bf16* owh, bf16* owl, bf16* gwh, bf16* gwl, bf16* uwh, bf16* uwl,
  bf16* dwh, bf16* dwl, bf16* tinh, bf16* tinl, bf16* touth, bf16* toutl,
  bf16* outwh, bf16* outwl, bf16* inwh, bf16* inwl, bf16* nh, bf16* nl,
  bf16* kh, bf16* kl, bf16* vh, bf16* vl)
{
  int cb = blockIdx.x, nb = gridDim.x;
  conv_gs(q_w,    qwh,   qwl,   2048*1024/4, cb, nb);
  conv_gs(k_w,    kwh,   kwl,   256*1024/4,  cb, nb);
  conv_gs(v_w,    vwh,   vwl,   256*1024/4,  cb, nb);
  conv_gs(o_w,    owh,   owl,   1024*2048/4, cb, nb);
  conv_gs(gate_w, gwh,   gwl,   4096*1024/4, cb, nb);
  conv_gs(up_w,   uwh,   uwl,   4096*1024/4, cb, nb);
  conv_gs(down_w, dwh,   dwl,   1024*4096/4, cb, nb);
  conv_gs(t_in_w, tinh,  tinl,  1024*2048/4, cb, nb);
  conv_gs(t_out_w,touth, toutl, 1024*1024/4, cb, nb);
  conv_gs(out_w,  outwh, outwl, 32*1024/4,   cb, nb);
  pad_gs(in_w,  inwh, inwl, 1024, cb, nb);
  pad_gs(noisy, nh,   nl,   MTOT, cb, nb);
  conv_kvprefix(pk, pv, 0, kh, kl, vh, vl, cb, nb);
}

__device__ __forceinline__ float blk_reduce(float v, bool ismax) {
    __shared__ float sh[8];
    int lane = threadIdx.x & 31, wid = threadIdx.x >> 5;
    #pragma unroll
    for (int o = 16; o > 0; o >>= 1) {
        float w = __shfl_xor_sync(0xffffffffu, v, o);
        v = ismax ? fmaxf(v, w) : (v + w);
    }
    if (lane == 0) sh[wid] = v;
    __syncthreads();
    if (threadIdx.x == 0) {
        float r = sh[0];
        int nw = (blockDim.x + 31) >> 5;
        for (int i = 1; i < nw; i++) r = ismax ? fmaxf(r, sh[i]) : (r + sh[i]);
        sh[0] = r;
    }
    __syncthreads();
    float r = sh[0];
    __syncthreads();
    return r;
}

// ---------------- GEMM stage loader (48KB: Ah16K,Al16K,Bh8K,Bl8K) ----------------
__device__ __forceinline__ void load_stage(char* st,
  const bf16* Ah, const bf16* Al, const bf16* Bh, const bf16* Bl,
  int lda, int ldb, int k0, int tid)
{
  char* sAh = st; char* sAl = st+16384; char* sBh = st+32768; char* sBl = st+40960;
  int r0 = tid>>3, ch = tid&7;
  #pragma unroll
  for(int e=0;e<4;e++){
    int r = r0 + e*32;
    int off = swz(r, ch*16);
    cpa16(sAh+off, Ah + (size_t)r*lda + k0 + ch*8);
    cpa16(sAl+off, Al + (size_t)r*lda + k0 + ch*8);
  }
  #pragma unroll
  for(int e=0;e<2;e++){
    int r = r0 + e*32;
    int off = swz(r, ch*16);
    cpa16(sBh+off, Bh + (size_t)r*ldb + k0 + ch*8);
    cpa16(sBl+off, Bl + (size_t)r*ldb + k0 + ch*8);
  }
}

__device__ __forceinline__ void compute_stage(char* st, float acc[2][4][4], int lane, int wm, int wn)
{
  char* sAh = st; char* sAl = st+16384; char* sBh = st+32768; char* sBl = st+40960;
  #pragma unroll
  for(int kk=0;kk<4;kk++){
    unsigned Ah[2][4], Al[2][4], Bh[4][2], Bl[4][2];
    #pragma unroll
    for(int mt=0;mt<2;mt++){
      int r = wm + mt*16 + (lane & 15);
      int cb = kk*32 + ((lane >> 4) << 4);
      int off = swz(r, cb);
      ldsm4(Ah[mt][0],Ah[mt][1],Ah[mt][2],Ah[mt][3], su32(sAh + off));
      ldsm4(Al[mt][0],Al[mt][1],Al[mt][2],Al[mt][3], su32(sAl + off));
    }
    #pragma unroll
    for(int p=0;p<2;p++){
      int r = wn + p*16 + (lane & 15);
      int cb = kk*32 + ((lane >> 4) << 4);
      int off = swz(r, cb);
      unsigned r0,r1,r2,r3;
      ldsm4(r0,r1,r2,r3, su32(sBh + off));
      Bh[p*2][0]=r0; Bh[p*2][1]=r2; Bh[p*2+1][0]=r1; Bh[p*2+1][1]=r3;
      ldsm4(r0,r1,r2,r3, su32(sBl + off));
      Bl[p*2][0]=r0; Bl[p*2][1]=r2; Bl[p*2+1][0]=r1; Bl[p*2+1][1]=r3;
    }
    #pragma unroll
    for(int mt=0;mt<2;mt++)
      #pragma unroll
      for(int ns=0;ns<4;ns++){
        mma16816(acc[mt][ns], Ah[mt], Bh[ns][0], Bh[ns][1]);
        mma16816(acc[mt][ns], Ah[mt], Bl[ns][0], Bl[ns][1]);
        mma16816(acc[mt][ns], Al[mt], Bh[ns][0], Bh[ns][1]);
      }
  }
}

// shared 2-stage mainloop
__device__ __forceinline__ void mainloop2(
  float acc[2][4][4], const bf16* Ahp, const bf16* Alp, const bf16* Bhp, const bf16* Blp,
  int lda, int ldb, int nk, int tid, int lane, int wm, int wn, char* st0, char* st1)
{
  load_stage(st0, Ahp, Alp, Bhp, Blp, lda, ldb, 0, tid);
  asm volatile("cp.async.commit_group;\n");
  for(int i=0;i<nk;i++){
    if(i+1 < nk){
      load_stage((i&1)?st0:st1, Ahp, Alp, Bhp, Blp, lda, ldb, (i+1)<<6, tid);
      asm volatile("cp.async.commit_group;\n");
      asm volatile("cp.async.wait_group 1;\n");
    } else {
      asm volatile("cp.async.wait_group 0;\n");
    }
    __syncthreads();
    compute_stage((i&1)?st1:st0, acc, lane, wm, wn);
    __syncthreads();
  }
}

// EPI bits: 1=bias (z==0 slice only), 2=residual fp32 read-add, 4=silu, 8=store bf16 hi/lo, 16=atomicAdd fp32
template<int EPI>
__global__ void __launch_bounds__(256,2) gemm_bf(
  const bf16* Ah, const bf16* Al, const bf16* Bh, const bf16* Bl,
  const float* bias, float* Cf, bf16* Ch, bf16* Cl,
  int M, int N, int K, int lda, int ldb, int ldc)
{
  extern __shared__ char rawsm[];
  char* st0 = rawsm; char* st1 = rawsm + 49152;
  int tid = threadIdx.x, lane = tid&31, warp = tid>>5;
  int wm = (warp>>1)*32, wn = (warp&1)*32;
  int m0 = blockIdx.y*128, n0 = blockIdx.x*64;
  size_t kofs = (size_t)blockIdx.z * K;
  const float* bz = (blockIdx.z == 0) ? bias : nullptr;

  float acc[2][4][4];
  #pragma unroll
  for(int i=0;i<2;i++)
    #pragma unroll
    for(int j=0;j<4;j++)
      #pragma unroll
      for(int e=0;e<4;e++) acc[i][j][e]=0.f;

  mainloop2(acc, Ah + (size_t)m0*lda + kofs, Al + (size_t)m0*lda + kofs,
            Bh + (size_t)n0*ldb + kofs, Bl + (size_t)n0*ldb + kofs,
            lda, ldb, K>>6, tid, lane, wm, wn, st0, st1);

  #pragma unroll
  for(int mt=0;mt<2;mt++)
    #pragma unroll
    for(int ns=0;ns<4;ns++){
      int row = m0 + wm + mt*16 + (lane>>2);
      int col = n0 + wn + ns*8 + (lane&3)*2;
      #pragma unroll
      for(int e=0;e<4;e++){
        int rr = row + ((e>=2)?8:0);
        int cc = col + (e&1);
        if(rr < M && cc < N){
          float v = acc[mt][ns][e];
          if((EPI&1) && bz) v += bz[cc];
          if(EPI&4) v = v/(1.f+expf(-v));
          if(EPI&16){
            atomicAdd(&Cf[(size_t)rr*ldc+cc], v);
          } else if(EPI&8){
            unsigned short h,l; split1(v,h,l);
            Ch[(size_t)rr*ldc+cc] = __ushort_as_bfloat16(h);
            Cl[(size_t)rr*ldc+cc] = __ushort_as_bfloat16(l);
          } else {
            if(EPI&2) v += Cf[(size_t)rr*ldc+cc];
            Cf[(size_t)rr*ldc+cc] = v;
          }
        }
      }
    }
}

// fused QKV: split-K x2 on z in {0,1} -> plain store into per-slice buffer; z in {2..6} converts NEXT layer's gate/up/down
__global__ void __launch_bounds__(256,2) qkv_gemm(
  const bf16* Ah, const bf16* Al,
  const bf16* qwh, const bf16* qwl, const bf16* kwh, const bf16* kwl,
  const bf16* vwh, const bf16* vwl,
  float* qkv, int layer,
  const float* gate_w, const float* up_w, const float* down_w,
  bf16* gwh, bf16* gwl, bf16* uwh, bf16* uwl, bf16* dwh, bf16* dwl)
{
  extern __shared__ char rawsm[];
  if (blockIdx.z >= 2) {
    int nl = layer + 1;
    if (nl < LNUM) {
      int cb = (blockIdx.z - 2)*160 + blockIdx.y*40 + blockIdx.x;
      const int nb = 5*160;
      const int n4 = 4096*1024/4;
      size_t o = (size_t)nl*4096*1024;
      conv_gs(gate_w + o, gwh + o, gwl + o, n4, cb, nb);
      conv_gs(up_w   + o, uwh + o, uwl + o, n4, cb, nb);
      conv_gs(down_w + o, dwh + o, dwl + o, n4, cb, nb);
    }
    return;
  }
  char* st0 = rawsm; char* st1 = rawsm + 49152;
  int bx = blockIdx.x, m0 = blockIdx.y*128;
  size_t kofs = (size_t)blockIdx.z * 512;
  float* C = qkv + (size_t)blockIdx.z * MTOT * QKVLD;
  const bf16 *Bh, *Bl; int n0, cbase;
  if (bx < 32) {
    size_t w = (size_t)layer*2048*1024;
    Bh = qwh + w; Bl = qwl + w; n0 = bx*64; cbase = n0;
  } else if (bx < 36) {
    size_t w = (size_t)layer*256*1024;
    Bh = kwh + w; Bl = kwl + w; n0 = (bx-32)*64; cbase = 2048 + n0;
  } else {
    size_t w = (size_t)layer*256*1024;
    Bh = vwh + w; Bl = vwl + w; n0 = (bx-36)*64; cbase = 2304 + n0;
  }
  int tid = threadIdx.x, lane = tid&31, warp = tid>>5;
  int wm = (warp>>1)*32, wn = (warp&1)*32;

  float acc[2][4][4];
  #pragma unroll
  for(int i=0;i<2;i++)
    #pragma unroll
    for(int j=0;j<4;j++)
      #pragma unroll
      for(int e=0;e<4;e++) acc[i][j][e]=0.f;

  mainloop2(acc, Ah + (size_t)m0*1024 + kofs, Al + (size_t)m0*1024 + kofs,
            Bh + (size_t)n0*1024 + kofs, Bl + (size_t)n0*1024 + kofs,
            1024, 1024, 8, tid, lane, wm, wn, st0, st1);

  #pragma unroll
  for(int mt=0;mt<2;mt++)
    #pragma unroll
    for(int ns=0;ns<4;ns++){
      int row = m0 + wm + mt*16 + (lane>>2);
      int col = cbase + wn + ns*8 + (lane&3)*2;
      #pragma unroll
      for(int e=0;e<4;e++){
        int rr = row + ((e>=2)?8:0);
        int cc = col + (e&1);
        if(rr < MTOT)
          C[(size_t)rr*QKVLD+cc] = acc[mt][ns][e];
      }
    }
}

// gate/up on z in {0,1}; z {2,3}: next layer's q/k/v/o weights; z {4,5}: next layer's KV prefix
__global__ void __launch_bounds__(256,2) gateup_gemm(
  const bf16* Ah, const bf16* Al,
  const bf16* gwh, const bf16* gwl, const bf16* uwh, const bf16* uwl,
  float* gate, float* up, int layer,
  const float* q_w, const float* k_w, const float* v_w, const float* o_w,
  bf16* qwh, bf16* qwl, bf16* kwh, bf16* kwl, bf16* vwh, bf16* vwl, bf16* owh, bf16* owl,
  const float* pk, const float* pv, bf16* kvkh, bf16* kvkl, bf16* kvvh, bf16* kvvl)
{
  extern __shared__ char rawsm[];
  if (blockIdx.z >= 4) {
    int nl = layer + 1;
    if (nl < LNUM) {
      int cb = (blockIdx.z - 4)*256 + blockIdx.y*64 + blockIdx.x;
      conv_kvprefix(pk, pv, nl, kvkh, kvkl, kvvh, kvvl, cb, 512);
    }
    return;
  }
  if (blockIdx.z >= 2) {
    int nl = layer + 1;
    if (nl < LNUM) {
      int cb = (blockIdx.z - 2)*256 + blockIdx.y*64 + blockIdx.x;
      const int nb = 2*256;
      size_t oq = (size_t)nl*2048*1024;
      size_t ok = (size_t)nl*256*1024;
      conv_gs(q_w + oq, qwh + oq, qwl + oq, 2048*1024/4, cb, nb);
      conv_gs(k_w + ok, kwh + ok, kwl + ok, 256*1024/4, cb, nb);
      conv_gs(v_w + ok, vwh + ok, vwl + ok, 256*1024/4, cb, nb);
      conv_gs(o_w + oq, owh + oq, owl + oq, 2048*1024/4, cb, nb);
    }
    return;
  }
  char* st0 = rawsm; char* st1 = rawsm + 49152;
  size_t w = (size_t)layer*4096*1024;
  const bf16* Bh = blockIdx.z ? (uwh+w) : (gwh+w);
  const bf16* Bl = blockIdx.z ? (uwl+w) : (gwl+w);
  float* C = blockIdx.z ? up : gate;
  int tid = threadIdx.x, lane = tid&31, warp = tid>>5;
  int wm = (warp>>1)*32, wn = (warp&1)*32;
  int m0 = blockIdx.y*128, n0 = blockIdx.x*64;

  float acc[2][4][4];
  #pragma unroll
  for(int i=0;i<2;i++)
    #pragma unroll
    for(int j=0;j<4;j++)
      #pragma unroll
      for(int e=0;e<4;e++) acc[i][j][e]=0.f;

  mainloop2(acc, Ah + (size_t)m0*1024, Al + (size_t)m0*1024,
            Bh + (size_t)n0*1024, Bl + (size_t)n0*1024,
            1024, 1024, 16, tid, lane, wm, wn, st0, st1);

  #pragma unroll
  for(int mt=0;mt<2;mt++)
    #pragma unroll
    for(int ns=0;ns<4;ns++){
      int row = m0 + wm + mt*16 + (lane>>2);
      int col = n0 + wn + ns*8 + (lane&3)*2;
      #pragma unroll
      for(int e=0;e<4;e++){
        int rr = row + ((e>=2)?8:0);
        int cc = col + (e&1);
        if(rr < MTOT)
          C[(size_t)rr*4096+cc] = acc[mt][ns][e];
      }
    }
}

// ---------------- silu + bf16 split ----------------
__global__ void silu_split(const float* __restrict__ in, bf16* __restrict__ oh, bf16* __restrict__ ol, int n)
{
  int i = blockIdx.x*blockDim.x + threadIdx.x;
  if (i >= n) return;
  float v = in[i];
  v = v/(1.f+expf(-v));
  unsigned short h, l;
  split1(v, h, l);
  oh[i] = __ushort_as_bfloat16(h);
  ol[i] = __ushort_as_bfloat16(l);
}

// ---------------- attention scores: head-pair blocks ----------------
__global__ void __launch_bounds__(256,2) attn_scores(
  const bf16* __restrict__ qh, const bf16* __restrict__ ql,
  const bf16* __restrict__ kh, const bf16* __restrict__ kl,
  float* __restrict__ S)
{
  extern __shared__ char rawsm[];
  char* st0 = rawsm; char* st1 = rawsm + 49152;
  int t0 = blockIdx.x * 64;
  int bp = blockIdx.y;
  int b = bp >> 2, hp = bp & 3;
  int zbase = b*NHH + hp*2;
  int tid = threadIdx.x, lane = tid&31, warp = tid>>5;
  int wm = (warp>>1)*32, wn = (warp&1)*32;

  float acc[2][4][4];
  #pragma unroll
  for(int i=0;i<2;i++)
    #pragma unroll
    for(int j=0;j<4;j++)
      #pragma unroll
      for(int e=0;e<4;e++) acc[i][j][e]=0.f;

  mainloop2(acc, qh + (size_t)zbase*CP*HD, ql + (size_t)zbase*CP*HD,
            kh + ((size_t)b*TP + t0)*HD, kl + ((size_t)b*TP + t0)*HD,
            HD, HD, HD/64, tid, lane, wm, wn, st0, st1);

  float* Sb = S + (size_t)zbase*CP*TP;
  #pragma unroll
  for(int mt=0;mt<2;mt++)
    #pragma unroll
    for(int ns=0;ns<4;ns++){
      int row = wm + mt*16 + (lane>>2);
      int col = t0 + wn + ns*8 + (lane&3)*2;
      Sb[(size_t)row*TP + col]          = acc[mt][ns][0];
      Sb[(size_t)row*TP + col + 1]      = acc[mt][ns][1];
      Sb[(size_t)(row+8)*TP + col]      = acc[mt][ns][2];
      Sb[(size_t)(row+8)*TP + col + 1]  = acc[mt][ns][3];
    }
}

// ---------------- attention AV: head-pair blocks, trans-B V ----------------
__device__ __forceinline__ void av_load(char* st,
  const bf16* Agh, const bf16* Agl, const bf16* Bgh, const bf16* Bgl, int k0, int tid)
{
  char* sAh = st; char* sAl = st+16384; char* sBh = st+32768; char* sBl = st+40960;
  int r0 = tid>>3, ch = tid&7;
  #pragma unroll
  for(int e=0;e<4;e++){
    int r = r0 + e*32;
    int off = swz(r, ch*16);
    cpa16(sAh+off, Agh + (size_t)r*TP + k0 + ch*8);
    cpa16(sAl+off, Agl + (size_t)r*TP + k0 + ch*8);
  }
  #pragma unroll
  for(int e=0;e<2;e++){
    int r = r0 + e*32;
    int off = swz(r, ch*16);
    cpa16(sBh+off, Bgh + (size_t)(k0 + r)*HD + ch*8);
    cpa16(sBl+off, Bgl + (size_t)(k0 + r)*HD + ch*8);
  }
}

__device__ __forceinline__ void av_compute(char* st, float acc[2][4][4], int lane, int wm, int wn)
{
  char* sAh = st; char* sAl = st+16384; char* sBh = st+32768; char* sBl = st+40960;
  #pragma unroll
  for(int kk=0;kk<4;kk++){
    unsigned Ah[2][4], Al[2][4], Bh[4][2], Bl[4][2];
    #pragma unroll
    for(int mt=0;mt<2;mt++){
      int r = wm + mt*16 + (lane & 15);
      int cb = kk*32 + ((lane >> 4) << 4);
      int off = swz(r, cb);
      ldsm4(Ah[mt][0],Ah[mt][1],Ah[mt][2],Ah[mt][3], su32(sAh + off));
      ldsm4(Al[mt][0],Al[mt][1],Al[mt][2],Al[mt][3], su32(sAl + off));
    }
    #pragma unroll
    for(int p=0;p<2;p++){
      int r = kk*16 + (lane & 15);
      int cb = (wn + p*16)*2 + ((lane >> 4) << 4);
      int off = swz(r, cb);
      unsigned r0,r1,r2,r3;
      ldsm4t(r0,r1,r2,r3, su32(sBh + off));
      Bh[p*2][0]=r0; Bh[p*2][1]=r1; Bh[p*2+1][0]=r2; Bh[p*2+1][1]=r3;
      ldsm4t(r0,r1,r2,r3, su32(sBl + off));
      Bl[p*2][0]=r0; Bl[p*2][1]=r1; Bl[p*2+1][0]=r2; Bl[p*2+1][1]=r3;
    }
    #pragma unroll
    for(int mt=0;mt<2;mt++)
      #pragma unroll
      for(int ns=0;ns<4;ns++){
        mma16816(acc[mt][ns], Ah[mt], Bh[ns][0], Bh[ns][1]);
        mma16816(acc[mt][ns], Ah[mt], Bl[ns][0], Bl[ns][1]);
        mma16816(acc[mt][ns], Al[mt], Bh[ns][0], Bh[ns][1]);
      }
  }
}

__global__ void __launch_bounds__(256,2) attn_av(
  const bf16* __restrict__ sh_, const bf16* __restrict__ sl_,
  const bf16* __restrict__ vh, const bf16* __restrict__ vl,
  bf16* __restrict__ Oh, bf16* __restrict__ Ol)
{
  extern __shared__ char rawsm[];
  char* st0 = rawsm; char* st1 = rawsm + 49152;
  int d0 = blockIdx.x * 64;
  int bp = blockIdx.y;
  int b = bp >> 2, hp = bp & 3;
  int zbase = b*NHH + hp*2;
  int tid = threadIdx.x, lane = tid&31, warp = tid>>5;
  int wm = (warp>>1)*32, wn = (warp&1)*32;
  const bf16* Agh = sh_ + (size_t)zbase*CP*TP;
  const bf16* Agl = sl_ + (size_t)zbase*CP*TP;
  const bf16* Bgh = vh + (size_t)b*TP*HD + d0;
  const bf16* Bgl = vl + (size_t)b*TP*HD + d0;

  float acc[2][4][4];
  #pragma unroll
  for(int i=0;i<2;i++)
    #pragma unroll
    for(int j=0;j<4;j++)
      #pragma unroll
      for(int e=0;e<4;e++) acc[i][j][e]=0.f;

  const int nk = TP/64;  // 14
  av_load(st0, Agh, Agl, Bgh, Bgl, 0, tid);
  asm volatile("cp.async.commit_group;\n");
  for(int i=0;i<nk;i++){
    if(i+1 < nk){
      av_load((i&1)?st0:st1, Agh, Agl, Bgh, Bgl, (i+1)<<6, tid);
      asm volatile("cp.async.commit_group;\n");
      asm volatile("cp.async.wait_group 1;\n");
    } else {
      asm volatile("cp.async.wait_group 0;\n");
    }
    __syncthreads();
    av_compute((i&1)?st1:st0, acc, lane, wm, wn);
    __syncthreads();
  }

  #pragma unroll
  for(int mt=0;mt<2;mt++)
    #pragma unroll
    for(int ns=0;ns<4;ns++){
      int row = wm + mt*16 + (lane>>2);
      int d = d0 + wn + ns*8 + (lane&3)*2;
      #pragma unroll
      for(int e=0;e<4;e++){
        int rr = row + ((e>=2)?8:0);
        int dd = d + (e&1);
        int hd2 = hp*2 + (rr>>6);
        int c = rr & 63;
        if(c < CC){
          unsigned short h, l;
          split1(acc[mt][ns][e], h, l);
          size_t idx = ((size_t)(b*CC + c))*(NHH*HD) + hd2*HD + dd;
          Oh[idx] = __ushort_as_bfloat16(h);
          Ol[idx] = __ushort_as_bfloat16(l);
        }
      }
    }
}

__global__ void __launch_bounds__(256) softmax_kernel(
  const float* __restrict__ S, bf16* __restrict__ Sh, bf16* __restrict__ Sl)
{
  int row = blockIdx.x;
  int z = row / CC, c = row % CC;
  const float* s = S + ((size_t)z*CP + c)*TP;
  float vals[4];
  float mx = -1e30f;
  #pragma unroll
  for (int ii = 0; ii < 4; ii++) {
    int j = threadIdx.x + ii*256;
    vals[ii] = (j < TTOT) ? s[j] : -1e30f;
    mx = fmaxf(mx, vals[ii]);
  }
  mx = blk_reduce(mx, true);
  float sum = 0.f;
  #pragma unroll
  for (int ii = 0; ii < 4; ii++) {
    int j = threadIdx.x + ii*256;
    if (j < TTOT) { vals[ii] = expf(vals[ii] - mx); sum += vals[ii]; }
  }
  sum = blk_reduce(sum, false);
  float inv = 1.f / sum;
  size_t base = ((size_t)z*CP + c)*TP;
  #pragma unroll
  for (int ii = 0; ii < 4; ii++) {
    int j = threadIdx.x + ii*256;
    if (j < TTOT) {
      float p = vals[ii] * inv;
      unsigned short h, l;
      split1(p, h, l);
      Sh[base + j] = __ushort_as_bfloat16(h);
      Sl[base + j] = __ushort_as_bfloat16(l);
    }
  }
}

// ---------------- new-token q/k/v rope + split (prefix handled by prefetch) ----------------
__global__ void qkvconv_kernel(
  const float* __restrict__ qkv, const int* __restrict__ pos,
  bf16* __restrict__ qh, bf16* __restrict__ ql,
  bf16* __restrict__ kh, bf16* __restrict__ kl,
  bf16* __restrict__ vh, bf16* __restrict__ vl)
{
  const float* qkv1 = qkv + (size_t)MTOT*QKVLD;
  int idx = blockIdx.x * blockDim.x + threadIdx.x;
  unsigned short h, l;
  if (idx < NQ_ITEMS) {
    int i = idx & 127;
    int mn = idx >> 7;
    int n = mn & 7, m = mn >> 3;
    int b = m / CC, c = m % CC;
    size_t po = (size_t)m*QKVLD + n*HD;
    float x1 = qkv[po + i] + qkv1[po + i];
    float x2 = qkv[po + i + 128] + qkv1[po + i + 128];
    float ang = (float)pos[c] * expf(-(float)i * (9.210340371976184f/128.f));
    float sn, cs; sincosf(ang, &sn, &cs);
    float o1 = (x1*cs - x2*sn) * 0.0625f;
    float o2 = (x2*cs + x1*sn) * 0.0625f;
    size_t dst = ((size_t)(b*NHH + n)*CP + c)*HD;
    split1(o1, h, l); qh[dst+i] = __ushort_as_bfloat16(h); ql[dst+i] = __ushort_as_bfloat16(l);
    split1(o2, h, l); qh[dst+i+128] = __ushort_as_bfloat16(h); ql[dst+i+128] = __ushort_as_bfloat16(l);
  } else if (idx < NQ_ITEMS + NKNEW_ITEMS) {
    int j = idx - NQ_ITEMS;
    int d = j & 127;
    int bc = j >> 7;
    int c = bc % CC, b = bc / CC;
    size_t po = (size_t)(b*CC + c)*QKVLD + 2048;
    float x1 = qkv[po + d] + qkv1[po + d];
    float x2 = qkv[po + d + 128] + qkv1[po + d + 128];
    float ang = (float)pos[c] * expf(-(float)d * (9.210340371976184f/128.f));
    float sn, cs; sincosf(ang, &sn, &cs);
    float o1 = x1*cs - x2*sn;
    float o2 = x2*cs + x1*sn;
    size_t dst = ((size_t)b*TP + PP + c)*HD;
    split1(o1, h, l); kh[dst+d] = __ushort_as_bfloat16(h); kl[dst+d] = __ushort_as_bfloat16(l);
    split1(o2, h, l); kh[dst+d+128] = __ushort_as_bfloat16(h); kl[dst+d+128] = __ushort_as_bfloat16(l);
  } else if (idx < NQ_ITEMS + NKNEW_ITEMS + NVNEW_ITEMS) {
    int j = idx - NQ_ITEMS - NKNEW_ITEMS;
    int d = j & 255;
    int bc = j >> 8;
    int c = bc % CC, b = bc / CC;
    size_t po = (size_t)(b*CC + c)*QKVLD + 2304 + d;
    float x = qkv[po] + qkv1[po];
    split1(x, h, l);
    size_t dst = ((size_t)b*TP + PP + c)*HD;
    vh[dst+d] = __ushort_as_bfloat16(h);
    vl[dst+d] = __ushort_as_bfloat16(l);
  }
}

// ---------------- other elementwise ----------------
__global__ void __launch_bounds__(256) rmsnorm_bf(
  const float* __restrict__ x, const float* __restrict__ w,
  bf16* __restrict__ oh, bf16* __restrict__ ol)
{
  int row = blockIdx.x;
  const float* xr = x + (size_t)row*HH;
  float ss = 0.f;
  for (int j = threadIdx.x; j < HH; j += 256) { float v = xr[j]; ss += v*v; }
  ss = blk_reduce(ss, false);
  float sc = rsqrtf(ss * (1.f/HH) + 1e-6f);
  for (int j = threadIdx.x; j < HH; j += 256) {
    float v = xr[j] * sc * w[j];
    unsigned short h, l;
    split1(v, h, l);
    oh[(size_t)row*HH + j] = __ushort_as_bfloat16(h);
    ol[(size_t)row*HH + j] = __ushort_as_bfloat16(l);
  }
}

__global__ void timeemb_bf(const float* __restrict__ ts, bf16* __restrict__ xth, bf16* __restrict__ xtl)
{
  int idx = blockIdx.x * blockDim.x + threadIdx.x;
  if (idx >= MTOT*HH) return;
  int m = idx >> 10, j = idx & 1023;
  int b = m / CC;
  float t = ts[b];
  int i = (j < 512) ? j : (j - 512);
  float period = 4e-3f * expf((float)i * (6.907755278982137f/512.f));
  float ang = 6.283185307179586f * t / period;
  float v = (j < 512) ? sinf(ang) : cosf(ang);
  unsigned short h, l;
  split1(v, h, l);
  size_t dst = (size_t)m*(2*HH) + HH + j;
  xth[dst] = __ushort_as_bfloat16(h);
  xtl[dst] = __ushort_as_bfloat16(l);
}

__global__ void gelumul_bf(const float* __restrict__ gate, const float* __restrict__ up,
                           bf16* __restrict__ mh, bf16* __restrict__ ml)
{
  int idx = blockIdx.x * blockDim.x + threadIdx.x;
  if (idx >= MTOT*MLPD) return;
  float g = gate[idx];
  float t = tanhf(0.7978845608028654f * (g + 0.044715f*g*g*g));
  float v = 0.5f * g * (1.f + t) * up[idx];
  unsigned short h, l;
  split1(v, h, l);
  mh[idx] = __ushort_as_bfloat16(h);
  ml[idx] = __ushort_as_bfloat16(l);
}

// ---------------- orchestration ----------------
extern "C" void kernel_launch(void* const* d_in, const int* in_sizes, int n_in,
                              void* d_out, int out_size)
{
  const float* noisy   = (const float*)d_in[0];
  const float* tstep   = (const float*)d_in[1];
  const int*   pos_ids = (const int*)d_in[2];
  const float* pk      = (const float*)d_in[3];
  const float* pv      = (const float*)d_in[4];
  const float* in_w    = (const float*)d_in[5];
  const float* in_b    = (const float*)d_in[6];
  const float* t_in_w  = (const float*)d_in[7];
  const float* t_in_b  = (const float*)d_in[8];
  const float* t_out_w = (const float*)d_in[9];
  const float* t_out_b = (const float*)d_in[10];
  const float* out_w   = (const float*)d_in[11];
  const float* out_b   = (const float*)d_in[12];
  const float* fn_w    = (const float*)d_in[13];
  const float* ln1_w   = (const float*)d_in[14];
  const float* q_w     = (const float*)d_in[15];
  const float* k_w     = (const float*)d_in[16];
  const float* v_w     = (const float*)d_in[17];
  const float* o_w     = (const float*)d_in[18];
  const float* ln2_w   = (const float*)d_in[19];
  const float* gate_w  = (const float*)d_in[20];
  const float* up_w    = (const float*)d_in[21];
  const float* down_w  = (const float*)d_in[22];
  float* out = (float*)d_out;

  float *x,*qkv,*s,*gate,*up;
  bf16 *hh,*hl,*xth,*xtl,*midh,*midl,*aoh,*aol,*nh,*nl;
  bf16 *qh,*ql,*kh,*kl,*vh,*vl,*sh,*sl;
  bf16 *qwh,*qwl,*kwh,*kwl,*vwh,*vwl,*owh,*owl,*gwh,*gwl,*uwh,*uwl,*dwh,*dwl;
  bf16 *tinh,*tinl,*touth,*toutl,*outwh,*outwl,*inwh,*inwl;

  cudaGetSymbolAddress((void**)&x, g_x);
  cudaGetSymbolAddress((void**)&qkv, g_qkv);
  cudaGetSymbolAddress((void**)&s, g_s);
  cudaGetSymbolAddress((void**)&gate, g_gate);
  cudaGetSymbolAddress((void**)&up, g_up);
  cudaGetSymbolAddress((void**)&hh, g_hh);   cudaGetSymbolAddress((void**)&hl, g_hl);
  cudaGetSymbolAddress((void**)&xth, g_xth); cudaGetSymbolAddress((void**)&xtl, g_xtl);
  cudaGetSymbolAddress((void**)&midh, g_midh); cudaGetSymbolAddress((void**)&midl, g_midl);
  cudaGetSymbolAddress((void**)&aoh, g_aoh); cudaGetSymbolAddress((void**)&aol, g_aol);
  cudaGetSymbolAddress((void**)&nh, g_nh);   cudaGetSymbolAddress((void**)&nl, g_nl);
  cudaGetSymbolAddress((void**)&qh, g_qh);   cudaGetSymbolAddress((void**)&ql, g_ql);
  cudaGetSymbolAddress((void**)&kh, g_kh);   cudaGetSymbolAddress((void**)&kl, g_kl);
  cudaGetSymbolAddress((void**)&vh, g_vh);   cudaGetSymbolAddress((void**)&vl, g_vl);
  cudaGetSymbolAddress((void**)&sh, g_sh);   cudaGetSymbolAddress((void**)&sl, g_sl);
  cudaGetSymbolAddress((void**)&qwh, g_qwh); cudaGetSymbolAddress((void**)&qwl, g_qwl);
  cudaGetSymbolAddress((void**)&kwh, g_kwh); cudaGetSymbolAddress((void**)&kwl, g_kwl);
  cudaGetSymbolAddress((void**)&vwh, g_vwh); cudaGetSymbolAddress((void**)&vwl, g_vwl);
  cudaGetSymbolAddress((void**)&owh, g_owh); cudaGetSymbolAddress((void**)&owl, g_owl);
  cudaGetSymbolAddress((void**)&gwh, g_gwh); cudaGetSymbolAddress((void**)&gwl, g_gwl);
  cudaGetSymbolAddress((void**)&uwh, g_uwh); cudaGetSymbolAddress((void**)&uwl, g_uwl);
  cudaGetSymbolAddress((void**)&dwh, g_dwh); cudaGetSymbolAddress((void**)&dwl, g_dwl);
  cudaGetSymbolAddress((void**)&tinh, g_tinh);   cudaGetSymbolAddress((void**)&tinl, g_tinl);
  cudaGetSymbolAddress((void**)&touth, g_touth); cudaGetSymbolAddress((void**)&toutl, g_toutl);
  cudaGetSymbolAddress((void**)&outwh, g_outwh); cudaGetSymbolAddress((void**)&outwl, g_outwl);
  cudaGetSymbolAddress((void**)&inwh, g_inwh);   cudaGetSymbolAddress((void**)&inwl, g_inwl);

  cudaFuncSetAttribute(gemm_bf<9>,  cudaFuncAttributeMaxDynamicSharedMemorySize, SMEM_GEMM);
  cudaFuncSetAttribute(gemm_bf<17>, cudaFuncAttributeMaxDynamicSharedMemorySize, SMEM_GEMM);
  cudaFuncSetAttribute(gemm_bf<18>, cudaFuncAttributeMaxDynamicSharedMemorySize, SMEM_GEMM);
  cudaFuncSetAttribute(qkv_gemm,    cudaFuncAttributeMaxDynamicSharedMemorySize, SMEM_GEMM);
  cudaFuncSetAttribute(gateup_gemm, cudaFuncAttributeMaxDynamicSharedMemorySize, SMEM_GEMM);
  cudaFuncSetAttribute(attn_scores, cudaFuncAttributeMaxDynamicSharedMemorySize, SMEM_GEMM);
  cudaFuncSetAttribute(attn_av,     cudaFuncAttributeMaxDynamicSharedMemorySize, SMEM_GEMM);

  // ---- upfront conversion: ONE kernel (layer 0 + prologue weights + inputs + layer-0 KV prefix) ----
  convall<<<2048,256>>>(q_w, k_w, v_w, o_w, gate_w, up_w, down_w,
                        t_in_w, t_out_w, out_w, in_w, noisy, pk, pv,
                        qwh, qwl, kwh, kwl, vwh, vwl, owh, owl,
                        gwh, gwl, uwh, uwl, dwh, dwl,
                        tinh, tinl, touth, toutl, outwh, outwl,
                        inwh, inwl, nh, nl, kh, kl, vh, vl);

  // ---- prologue ----
  gemm_bf<9><<<dim3(16,4,1),256,SMEM_GEMM>>>(nh, nl, inwh, inwl, in_b, nullptr, xth, xtl,
                                             MTOT, 1024, 64, 64, 64, 2048);
  timeemb_bf<<<(MTOT*HH+255)/256,256>>>(tstep, xth, xtl);
  cudaMemsetAsync(gate, 0, (size_t)MTOT*1024*sizeof(float));
  gemm_bf<17><<<dim3(16,4,2),256,SMEM_GEMM>>>(xth, xtl, tinh, tinl, t_in_b, gate, nullptr, nullptr,
                                              MTOT, 1024, 1024, 2048, 2048, 1024);
  silu_split<<<(MTOT*1024+255)/256,256>>>(gate, hh, hl, MTOT*1024);
  cudaMemsetAsync(x, 0, (size_t)MTOT*HH*sizeof(float));
  gemm_bf<17><<<dim3(16,4,2),256,SMEM_GEMM>>>(hh, hl, touth, toutl, t_out_b, x, nullptr, nullptr,
                                              MTOT, 1024, 512, 1024, 1024, 1024);

  int convgrid = (NQ_ITEMS + NKNEW_ITEMS + NVNEW_ITEMS + 255)/256;
  for (int l = 0; l < LNUM; l++) {
    bf16* khl = kh + (size_t)(l&1)*KVSTRIDE;
    bf16* kll = kl + (size_t)(l&1)*KVSTRIDE;
    bf16* vhl = vh + (size_t)(l&1)*KVSTRIDE;
    bf16* vll = vl + (size_t)(l&1)*KVSTRIDE;

    rmsnorm_bf<<<MTOT,256>>>(x, ln1_w + l*HH, hh, hl);
    // z 0..1: QKV GEMM; z 2..6: convert layer l+1 gate/up/down weights
    qkv_gemm<<<dim3(40,4,7),256,SMEM_GEMM>>>(hh, hl, qwh, qwl, kwh, kwl, vwh, vwl, qkv, l,
                                             gate_w, up_w, down_w, gwh, gwl, uwh, uwl, dwh, dwl);
    qkvconv_kernel<<<convgrid,256>>>(qkv, pos_ids, qh, ql, khl, kll, vhl, vll);
    attn_scores<<<dim3(TP/64, BB*4),256,SMEM_GEMM>>>(qh, ql, khl, kll, s);
    softmax_kernel<<<BB*NHH*CC,256>>>(s, sh, sl);
    attn_av<<<dim3(HD/64, BB*4),256,SMEM_GEMM>>>(sh, sl, vhl, vll, aoh, aol);
    gemm_bf<18><<<dim3(16,4,4),256,SMEM_GEMM>>>(aoh, aol,
        owh + (size_t)l*1024*2048, owl + (size_t)l*1024*2048,
        nullptr, x, nullptr, nullptr, MTOT, 1024, 512, 2048, 2048, 1024);
    rmsnorm_bf<<<MTOT,256>>>(x, ln2_w + l*HH, hh, hl);
    // z 0..1: gate/up GEMM; z 2..3: layer l+1 q/k/v/o weights; z 4..5: layer l+1 KV prefix
    gateup_gemm<<<dim3(64,4,6),256,SMEM_GEMM>>>(hh, hl, gwh, gwl, uwh, uwl, gate, up, l,
                                                q_w, k_w, v_w, o_w,
                                                qwh, qwl, kwh, kwl, vwh, vwl, owh, owl,
                                                pk, pv, kh, kl, vh, vl);
    gelumul_bf<<<(MTOT*MLPD+255)/256,256>>>(gate, up, midh, midl);
    gemm_bf<18><<<dim3(16,4,4),256,SMEM_GEMM>>>(midh, midl,
        dwh + (size_t)l*1024*4096, dwl + (size_t)l*1024*4096,
        nullptr, x, nullptr, nullptr, MTOT, 1024, 1024, 4096, 4096, 1024);
  }

  rmsnorm_bf<<<MTOT,256>>>(x, fn_w, hh, hl);
  cudaMemsetAsync(out, 0, (size_t)MTOT*AA*sizeof(float));
  gemm_bf<17><<<dim3(1,4,8),256,SMEM_GEMM>>>(hh, hl, outwh, outwl, out_b, out, nullptr, nullptr,
                                             MTOT, 32, 128, 1024, 1024, 32);
}